// round 1
// baseline (speedup 1.0000x reference)
#include <cuda_runtime.h>
#include <cuda_bf16.h>
#include <math.h>

// Problem constants
#define BATCH   4
#define SEQ     2048
#define DMODEL  1024
#define NHEADS  16
#define DHEAD   64
#define MROWS   (BATCH * SEQ)          // 8192
#define NB_ELEM ((size_t)MROWS * DMODEL) // 8.39M floats per buffer

// Scratch: Q, K, V projections + attention output. 4 x 33.55 MB = 134 MB.
__device__ float g_bufs[4][MROWS * DMODEL];

// ---------------------------------------------------------------------------
// Tiled fp32 GEMM: C[M,N] = A[M,K] * B[K,N], all row-major.
// 64x64 block tile, BK=16, 256 threads, 4x4 per-thread micro-tile.
// A tile stored transposed in smem so both operands read as float4.
// ---------------------------------------------------------------------------
__global__ void sgemm64(const float* __restrict__ A, const float* __restrict__ B,
                        float* __restrict__ C, int M, int N, int K) {
    __shared__ float At[16][68];   // At[k][m], padded
    __shared__ float Bs[16][64];   // Bs[k][n]

    const int tid = threadIdx.x;
    const int tx = tid & 15;       // 0..15 -> n micro
    const int ty = tid >> 4;       // 0..15 -> m micro
    const int row0 = blockIdx.y * 64;
    const int col0 = blockIdx.x * 64;

    float acc[4][4] = {};

    const int ar = tid >> 2;            // 0..63
    const int ac4 = (tid & 3) * 4;      // 0,4,8,12
    const int bk = tid >> 4;            // 0..15
    const int bn4 = (tid & 15) * 4;     // 0..60

    for (int kt = 0; kt < K; kt += 16) {
        // Load A tile (64 x 16), transposed into At
        float4 av = *(const float4*)&A[(size_t)(row0 + ar) * K + kt + ac4];
        At[ac4 + 0][ar] = av.x;
        At[ac4 + 1][ar] = av.y;
        At[ac4 + 2][ar] = av.z;
        At[ac4 + 3][ar] = av.w;
        // Load B tile (16 x 64)
        *(float4*)&Bs[bk][bn4] = *(const float4*)&B[(size_t)(kt + bk) * N + col0 + bn4];
        __syncthreads();

        #pragma unroll
        for (int k = 0; k < 16; k++) {
            float4 a4 = *(const float4*)&At[k][ty * 4];
            float4 b4 = *(const float4*)&Bs[k][tx * 4];
            float ar_[4] = {a4.x, a4.y, a4.z, a4.w};
            float br_[4] = {b4.x, b4.y, b4.z, b4.w};
            #pragma unroll
            for (int i = 0; i < 4; i++)
                #pragma unroll
                for (int j = 0; j < 4; j++)
                    acc[i][j] += ar_[i] * br_[j];
        }
        __syncthreads();
    }

    #pragma unroll
    for (int i = 0; i < 4; i++) {
        float4 v = make_float4(acc[i][0], acc[i][1], acc[i][2], acc[i][3]);
        *(float4*)&C[(size_t)(row0 + ty * 4 + i) * N + col0 + tx * 4] = v;
    }
}

// ---------------------------------------------------------------------------
// In-place NeoX RoPE on Q and K (layout [B*S, H*DH]).
// One thread per (m, h, d<32) pair; owns both elements of the rotation pair.
// ---------------------------------------------------------------------------
__global__ void rope_kernel(float* __restrict__ Q, float* __restrict__ K,
                            const int* __restrict__ positions) {
    int idx = blockIdx.x * blockDim.x + threadIdx.x;
    // total = MROWS * NHEADS * 32
    if (idx >= MROWS * NHEADS * 32) return;
    int d = idx & 31;
    int h = (idx >> 5) & 15;
    int m = idx >> 9;                  // 0..8191
    int s = m & (SEQ - 1);

    float pos = (float)positions[s];
    // inv_freq = theta^(-d/32); compute in double for accuracy
    float inv_freq = (float)exp(-log(10000.0) * (double)d / 32.0);
    float ang = pos * inv_freq;
    float c, sn;
    sincosf(ang, &sn, &c);

    size_t base = (size_t)m * DMODEL + h * DHEAD + d;
    float q1 = Q[base], q2 = Q[base + 32];
    Q[base]      = q1 * c - q2 * sn;
    Q[base + 32] = q2 * c + q1 * sn;
    float k1 = K[base], k2 = K[base + 32];
    K[base]      = k1 * c - k2 * sn;
    K[base + 32] = k2 * c + k1 * sn;
}

// ---------------------------------------------------------------------------
// Flash attention (non-causal, scale = 1.0).
// grid: (S/64, B*H). 256 threads. BQ = BK = 64 tiles.
// Q/K/V layout: [B*S, H*DH] (head slice at column h*64).
// ---------------------------------------------------------------------------
struct AttnSmem {
    float Qt[64][68];   // Q^T : [d][q]
    float Kt[64][68];   // K^T : [d][k]
    float Vs[64][68];   // V   : [k][d]
    float Ps[64][68];   // scores/probs : [q][k]
    float m_run[64];
    float l_run[64];
    float alphas[64];
};

__global__ void attn_kernel(const float* __restrict__ Q, const float* __restrict__ K,
                            const float* __restrict__ V, float* __restrict__ O) {
    extern __shared__ char smem_raw[];
    AttnSmem& sm = *reinterpret_cast<AttnSmem*>(smem_raw);

    const int tid = threadIdx.x;
    const int tx = tid & 15;
    const int ty = tid >> 4;
    const int bh = blockIdx.y;
    const int b = bh >> 4;
    const int h = bh & 15;
    const int q0 = blockIdx.x * 64;
    const size_t base = (size_t)b * SEQ * DMODEL + (size_t)h * DHEAD;

    // Load Q tile transposed: Qt[d][r]
    {
        const int lr = tid >> 4;            // 0..15
        const int d4 = (tid & 15) * 4;      // 0..60
        #pragma unroll
        for (int i = 0; i < 4; i++) {
            int r = lr + i * 16;
            float4 qv = *(const float4*)&Q[base + (size_t)(q0 + r) * DMODEL + d4];
            sm.Qt[d4 + 0][r] = qv.x;
            sm.Qt[d4 + 1][r] = qv.y;
            sm.Qt[d4 + 2][r] = qv.z;
            sm.Qt[d4 + 3][r] = qv.w;
        }
    }
    if (tid < 64) { sm.m_run[tid] = -INFINITY; sm.l_run[tid] = 0.f; }

    float o[4][4] = {};

    for (int kt = 0; kt < SEQ; kt += 64) {
        __syncthreads();   // protect Kt/Vs vs previous iteration's reads; Qt before first use
        // Load K (transposed) and V tiles
        {
            const int lr = tid >> 4;
            const int d4 = (tid & 15) * 4;
            #pragma unroll
            for (int i = 0; i < 4; i++) {
                int r = lr + i * 16;
                float4 kv = *(const float4*)&K[base + (size_t)(kt + r) * DMODEL + d4];
                sm.Kt[d4 + 0][r] = kv.x;
                sm.Kt[d4 + 1][r] = kv.y;
                sm.Kt[d4 + 2][r] = kv.z;
                sm.Kt[d4 + 3][r] = kv.w;
                float4 vv = *(const float4*)&V[base + (size_t)(kt + r) * DMODEL + d4];
                *(float4*)&sm.Vs[r][d4] = vv;
            }
        }
        __syncthreads();

        // S = Q K^T (64x64), 4x4 per thread
        float s[4][4] = {};
        #pragma unroll 8
        for (int d = 0; d < DHEAD; d++) {
            float4 a4 = *(const float4*)&sm.Qt[d][ty * 4];
            float4 b4 = *(const float4*)&sm.Kt[d][tx * 4];
            float ar_[4] = {a4.x, a4.y, a4.z, a4.w};
            float br_[4] = {b4.x, b4.y, b4.z, b4.w};
            #pragma unroll
            for (int i = 0; i < 4; i++)
                #pragma unroll
                for (int j = 0; j < 4; j++)
                    s[i][j] += ar_[i] * br_[j];
        }
        #pragma unroll
        for (int i = 0; i < 4; i++) {
            float4 v = make_float4(s[i][0], s[i][1], s[i][2], s[i][3]);
            *(float4*)&sm.Ps[ty * 4 + i][tx * 4] = v;
        }
        __syncthreads();

        // Online-softmax row statistics (64 threads, one row each)
        if (tid < 64) {
            const int r = tid;
            float m_old = sm.m_run[r];
            float mx = m_old;
            #pragma unroll 8
            for (int c = 0; c < 64; c++) mx = fmaxf(mx, sm.Ps[r][c]);
            float al = expf(m_old - mx);     // exp(-inf)=0 on first tile
            float sum = 0.f;
            #pragma unroll 8
            for (int c = 0; c < 64; c++) {
                float p = expf(sm.Ps[r][c] - mx);
                sm.Ps[r][c] = p;
                sum += p;
            }
            sm.l_run[r] = sm.l_run[r] * al + sum;
            sm.m_run[r] = mx;
            sm.alphas[r] = al;
        }
        __syncthreads();

        // Rescale accumulator, then O += P @ V
        float al[4];
        #pragma unroll
        for (int i = 0; i < 4; i++) al[i] = sm.alphas[ty * 4 + i];
        #pragma unroll
        for (int i = 0; i < 4; i++)
            #pragma unroll
            for (int j = 0; j < 4; j++)
                o[i][j] *= al[i];

        #pragma unroll 8
        for (int kk = 0; kk < 64; kk++) {
            float4 b4 = *(const float4*)&sm.Vs[kk][tx * 4];
            float br_[4] = {b4.x, b4.y, b4.z, b4.w};
            float ar_[4];
            #pragma unroll
            for (int i = 0; i < 4; i++) ar_[i] = sm.Ps[ty * 4 + i][kk];
            #pragma unroll
            for (int i = 0; i < 4; i++)
                #pragma unroll
                for (int j = 0; j < 4; j++)
                    o[i][j] += ar_[i] * br_[j];
        }
    }

    // Normalize and write back into [B*S, H*DH] layout
    #pragma unroll
    for (int i = 0; i < 4; i++) {
        float inv = 1.f / sm.l_run[ty * 4 + i];
        float4 v = make_float4(o[i][0] * inv, o[i][1] * inv, o[i][2] * inv, o[i][3] * inv);
        *(float4*)&O[base + (size_t)(q0 + ty * 4 + i) * DMODEL + tx * 4] = v;
    }
}

// ---------------------------------------------------------------------------
// Launch: 3 GEMMs (Q,K,V) -> RoPE -> flash attention -> output GEMM.
// ---------------------------------------------------------------------------
extern "C" void kernel_launch(void* const* d_in, const int* in_sizes, int n_in,
                              void* d_out, int out_size) {
    const int*   positions = (const int*)d_in[0];
    const float* X  = (const float*)d_in[1];
    const float* wq = (const float*)d_in[2];
    const float* wk = (const float*)d_in[3];
    const float* wv = (const float*)d_in[4];
    const float* wo = (const float*)d_in[5];
    float* out = (float*)d_out;

    float* bufs = nullptr;
    cudaGetSymbolAddress((void**)&bufs, g_bufs);
    float* Qp = bufs;
    float* Kp = bufs + NB_ELEM;
    float* Vp = bufs + 2 * NB_ELEM;
    float* Op = bufs + 3 * NB_ELEM;

    dim3 ggrid(DMODEL / 64, MROWS / 64);   // (16, 128)
    sgemm64<<<ggrid, 256>>>(X, wq, Qp, MROWS, DMODEL, DMODEL);
    sgemm64<<<ggrid, 256>>>(X, wk, Kp, MROWS, DMODEL, DMODEL);
    sgemm64<<<ggrid, 256>>>(X, wv, Vp, MROWS, DMODEL, DMODEL);

    int pairs = MROWS * NHEADS * 32;
    rope_kernel<<<(pairs + 255) / 256, 256>>>(Qp, Kp, positions);

    int smem_bytes = (int)sizeof(AttnSmem);
    cudaFuncSetAttribute(attn_kernel, cudaFuncAttributeMaxDynamicSharedMemorySize, smem_bytes);
    attn_kernel<<<dim3(SEQ / 64, BATCH * NHEADS), 256, smem_bytes>>>(Qp, Kp, Vp, Op);

    sgemm64<<<ggrid, 256>>>(Op, wo, out, MROWS, DMODEL, DMODEL);
}

// round 2
// speedup vs baseline: 1.5613x; 1.5613x over previous
#include <cuda_runtime.h>
#include <cuda_bf16.h>
#include <math.h>

// Problem constants
#define BATCH   4
#define SEQ     2048
#define DMODEL  1024
#define NHEADS  16
#define DHEAD   64
#define MROWS   (BATCH * SEQ)            // 8192
#define NB_ELEM ((size_t)MROWS * DMODEL) // 8.39M floats per buffer

// Scratch: Q, K, V projections + attention output. 4 x 33.55 MB = 134 MB.
__device__ float g_bufs[4][MROWS * DMODEL];

// ---------------------------------------------------------------------------
// tf32 helpers
// ---------------------------------------------------------------------------
__device__ __forceinline__ float to_tf32(float x) {
    float r;
    asm("cvt.rna.tf32.f32 %0, %1;" : "=f"(r) : "f"(x));
    return r;
}

__device__ __forceinline__ void mma_tf32(float* c, const float* a, const float* b) {
    unsigned const* au = reinterpret_cast<unsigned const*>(a);
    unsigned const* bu = reinterpret_cast<unsigned const*>(b);
    asm volatile(
        "mma.sync.aligned.m16n8k8.row.col.f32.tf32.tf32.f32 "
        "{%0,%1,%2,%3}, {%4,%5,%6,%7}, {%8,%9}, {%0,%1,%2,%3};"
        : "+f"(c[0]), "+f"(c[1]), "+f"(c[2]), "+f"(c[3])
        : "r"(au[0]), "r"(au[1]), "r"(au[2]), "r"(au[3]),
          "r"(bu[0]), "r"(bu[1]));
}

// ---------------------------------------------------------------------------
// tf32 tensor-core GEMM: C[M,N] = A[M,K] * B[K,N], row-major.
// 128x128 tile, BK=16, 256 threads (8 warps as 4m x 2n), double-buffered smem.
// Warp tile 32x64 -> 2 m-tiles x 8 n-tiles of m16n8k8.
// ---------------------------------------------------------------------------
#define GBM 128
#define GBN 128
#define GBK 16

__global__ __launch_bounds__(256, 2)
void gemm_tf32(const float* __restrict__ A, const float* __restrict__ B,
               float* __restrict__ C, int M, int N, int K) {
    __shared__ float As[2][GBK][GBM + 4];   // [k][m], stride 132 (mod 32 == 4)
    __shared__ float Bs[2][GBK][GBN + 4];   // [k][n]

    const int tid  = threadIdx.x;
    const int lane = tid & 31;
    const int wid  = tid >> 5;
    const int wm   = wid & 3;               // 0..3 -> m offset 32*wm
    const int wn   = wid >> 2;              // 0..1 -> n offset 64*wn
    const int row0 = blockIdx.y * GBM;
    const int col0 = blockIdx.x * GBN;

    const int g  = lane >> 2;               // groupID 0..7
    const int tg = lane & 3;                // thread-in-group 0..3

    // global load indices
    const int ar  = tid >> 2;               // 0..63 (rows ar, ar+64)
    const int ac  = (tid & 3) * 4;          // k offset
    const int br  = tid >> 5;               // 0..7  (rows br, br+8)
    const int bc  = (tid & 31) * 4;         // n offset

    float acc[2][8][4];
    #pragma unroll
    for (int i = 0; i < 2; i++)
        #pragma unroll
        for (int j = 0; j < 8; j++)
            #pragma unroll
            for (int q = 0; q < 4; q++) acc[i][j][q] = 0.f;

    float4 a_reg[2], b_reg[2];

    // prologue: tile 0 -> stage 0
    a_reg[0] = *(const float4*)&A[(size_t)(row0 + ar) * K + ac];
    a_reg[1] = *(const float4*)&A[(size_t)(row0 + ar + 64) * K + ac];
    b_reg[0] = *(const float4*)&B[(size_t)br * N + col0 + bc];
    b_reg[1] = *(const float4*)&B[(size_t)(br + 8) * N + col0 + bc];
    {
        As[0][ac + 0][ar] = to_tf32(a_reg[0].x);
        As[0][ac + 1][ar] = to_tf32(a_reg[0].y);
        As[0][ac + 2][ar] = to_tf32(a_reg[0].z);
        As[0][ac + 3][ar] = to_tf32(a_reg[0].w);
        As[0][ac + 0][ar + 64] = to_tf32(a_reg[1].x);
        As[0][ac + 1][ar + 64] = to_tf32(a_reg[1].y);
        As[0][ac + 2][ar + 64] = to_tf32(a_reg[1].z);
        As[0][ac + 3][ar + 64] = to_tf32(a_reg[1].w);
        float4 v0 = make_float4(to_tf32(b_reg[0].x), to_tf32(b_reg[0].y),
                                to_tf32(b_reg[0].z), to_tf32(b_reg[0].w));
        float4 v1 = make_float4(to_tf32(b_reg[1].x), to_tf32(b_reg[1].y),
                                to_tf32(b_reg[1].z), to_tf32(b_reg[1].w));
        *(float4*)&Bs[0][br][bc]     = v0;
        *(float4*)&Bs[0][br + 8][bc] = v1;
    }
    __syncthreads();

    const int iters = K / GBK;
    for (int it = 0; it < iters; it++) {
        const int cur = it & 1;
        // prefetch next tile into registers
        if (it + 1 < iters) {
            int kt = (it + 1) * GBK;
            a_reg[0] = *(const float4*)&A[(size_t)(row0 + ar) * K + kt + ac];
            a_reg[1] = *(const float4*)&A[(size_t)(row0 + ar + 64) * K + kt + ac];
            b_reg[0] = *(const float4*)&B[(size_t)(kt + br) * N + col0 + bc];
            b_reg[1] = *(const float4*)&B[(size_t)(kt + br + 8) * N + col0 + bc];
        }

        // compute on stage cur: 2 k-steps of 8
        #pragma unroll
        for (int ks = 0; ks < GBK; ks += 8) {
            float a[2][4];
            #pragma unroll
            for (int mi = 0; mi < 2; mi++) {
                int m0 = wm * 32 + mi * 16;
                a[mi][0] = As[cur][ks + tg][m0 + g];
                a[mi][1] = As[cur][ks + tg][m0 + g + 8];
                a[mi][2] = As[cur][ks + 4 + tg][m0 + g];
                a[mi][3] = As[cur][ks + 4 + tg][m0 + g + 8];
            }
            #pragma unroll
            for (int ni = 0; ni < 8; ni++) {
                int n0 = wn * 64 + ni * 8;
                float b[2];
                b[0] = Bs[cur][ks + tg][n0 + g];
                b[1] = Bs[cur][ks + 4 + tg][n0 + g];
                mma_tf32(acc[0][ni], a[0], b);
                mma_tf32(acc[1][ni], a[1], b);
            }
        }

        if (it + 1 < iters) {
            const int nxt = cur ^ 1;
            As[nxt][ac + 0][ar] = to_tf32(a_reg[0].x);
            As[nxt][ac + 1][ar] = to_tf32(a_reg[0].y);
            As[nxt][ac + 2][ar] = to_tf32(a_reg[0].z);
            As[nxt][ac + 3][ar] = to_tf32(a_reg[0].w);
            As[nxt][ac + 0][ar + 64] = to_tf32(a_reg[1].x);
            As[nxt][ac + 1][ar + 64] = to_tf32(a_reg[1].y);
            As[nxt][ac + 2][ar + 64] = to_tf32(a_reg[1].z);
            As[nxt][ac + 3][ar + 64] = to_tf32(a_reg[1].w);
            float4 v0 = make_float4(to_tf32(b_reg[0].x), to_tf32(b_reg[0].y),
                                    to_tf32(b_reg[0].z), to_tf32(b_reg[0].w));
            float4 v1 = make_float4(to_tf32(b_reg[1].x), to_tf32(b_reg[1].y),
                                    to_tf32(b_reg[1].z), to_tf32(b_reg[1].w));
            *(float4*)&Bs[nxt][br][bc]     = v0;
            *(float4*)&Bs[nxt][br + 8][bc] = v1;
        }
        __syncthreads();
    }

    // epilogue
    #pragma unroll
    for (int mi = 0; mi < 2; mi++) {
        #pragma unroll
        for (int ni = 0; ni < 8; ni++) {
            int rg = row0 + wm * 32 + mi * 16 + g;
            int cg = col0 + wn * 64 + ni * 8 + tg * 2;
            *(float2*)&C[(size_t)rg * N + cg]       = make_float2(acc[mi][ni][0], acc[mi][ni][1]);
            *(float2*)&C[(size_t)(rg + 8) * N + cg] = make_float2(acc[mi][ni][2], acc[mi][ni][3]);
        }
    }
}

// ---------------------------------------------------------------------------
// In-place NeoX RoPE on Q and K (layout [B*S, H*DH]). No fp64.
// ---------------------------------------------------------------------------
__global__ void rope_kernel(float* __restrict__ Q, float* __restrict__ K,
                            const int* __restrict__ positions) {
    int idx = blockIdx.x * blockDim.x + threadIdx.x;
    if (idx >= MROWS * NHEADS * 32) return;
    int d = idx & 31;
    int h = (idx >> 5) & 15;
    int m = idx >> 9;
    int s = m & (SEQ - 1);

    float pos = (float)positions[s];
    // inv_freq = 10000^(-d/32) = 2^(-d * log2(10000)/32)
    float inv_freq = exp2f((float)d * -0.4152410118609203f);
    float ang = pos * inv_freq;
    float c, sn;
    sincosf(ang, &sn, &c);

    size_t base = (size_t)m * DMODEL + h * DHEAD + d;
    float q1 = Q[base], q2 = Q[base + 32];
    Q[base]      = q1 * c - q2 * sn;
    Q[base + 32] = q2 * c + q1 * sn;
    float k1 = K[base], k2 = K[base + 32];
    K[base]      = k1 * c - k2 * sn;
    K[base + 32] = k2 * c + k1 * sn;
}

// ---------------------------------------------------------------------------
// Flash attention (non-causal, scale = 1.0). FFMA compute, parallel softmax.
// grid: (S/64, B*H). 256 threads. BQ = BK = 64 tiles.
// ---------------------------------------------------------------------------
struct AttnSmem {
    float Qt[64][68];   // Q^T : [d][q]
    float Kt[64][68];   // K^T : [d][k]
    float Vs[64][68];   // V   : [k][d]
    float Ps[64][68];   // scores/probs : [q][k]
    float m_run[64];
    float l_run[64];
    float alphas[64];
};

__global__ void attn_kernel(const float* __restrict__ Q, const float* __restrict__ K,
                            const float* __restrict__ V, float* __restrict__ O) {
    extern __shared__ char smem_raw[];
    AttnSmem& sm = *reinterpret_cast<AttnSmem*>(smem_raw);

    const int tid = threadIdx.x;
    const int tx = tid & 15;
    const int ty = tid >> 4;
    const int bh = blockIdx.y;
    const int b = bh >> 4;
    const int h = bh & 15;
    const int q0 = blockIdx.x * 64;
    const size_t base = (size_t)b * SEQ * DMODEL + (size_t)h * DHEAD;

    // Load Q tile transposed: Qt[d][r]
    {
        const int lr = tid >> 4;
        const int d4 = (tid & 15) * 4;
        #pragma unroll
        for (int i = 0; i < 4; i++) {
            int r = lr + i * 16;
            float4 qv = *(const float4*)&Q[base + (size_t)(q0 + r) * DMODEL + d4];
            sm.Qt[d4 + 0][r] = qv.x;
            sm.Qt[d4 + 1][r] = qv.y;
            sm.Qt[d4 + 2][r] = qv.z;
            sm.Qt[d4 + 3][r] = qv.w;
        }
    }
    if (tid < 64) { sm.m_run[tid] = -INFINITY; sm.l_run[tid] = 0.f; }

    float o[4][4] = {};

    for (int kt = 0; kt < SEQ; kt += 64) {
        __syncthreads();
        // Load K (transposed) and V tiles
        {
            const int lr = tid >> 4;
            const int d4 = (tid & 15) * 4;
            #pragma unroll
            for (int i = 0; i < 4; i++) {
                int r = lr + i * 16;
                float4 kv = *(const float4*)&K[base + (size_t)(kt + r) * DMODEL + d4];
                sm.Kt[d4 + 0][r] = kv.x;
                sm.Kt[d4 + 1][r] = kv.y;
                sm.Kt[d4 + 2][r] = kv.z;
                sm.Kt[d4 + 3][r] = kv.w;
                float4 vv = *(const float4*)&V[base + (size_t)(kt + r) * DMODEL + d4];
                *(float4*)&sm.Vs[r][d4] = vv;
            }
        }
        __syncthreads();

        // S = Q K^T (64x64), 4x4 per thread
        float s[4][4] = {};
        #pragma unroll 8
        for (int d = 0; d < DHEAD; d++) {
            float4 a4 = *(const float4*)&sm.Qt[d][ty * 4];
            float4 b4 = *(const float4*)&sm.Kt[d][tx * 4];
            float ar_[4] = {a4.x, a4.y, a4.z, a4.w};
            float br_[4] = {b4.x, b4.y, b4.z, b4.w};
            #pragma unroll
            for (int i = 0; i < 4; i++)
                #pragma unroll
                for (int j = 0; j < 4; j++)
                    s[i][j] += ar_[i] * br_[j];
        }
        #pragma unroll
        for (int i = 0; i < 4; i++) {
            float4 v = make_float4(s[i][0], s[i][1], s[i][2], s[i][3]);
            *(float4*)&sm.Ps[ty * 4 + i][tx * 4] = v;
        }
        __syncthreads();

        // Online-softmax: 4 threads per row, lane-strided columns (conflict-free)
        {
            const int r = tid >> 2;
            const int q = tid & 3;
            float m_old = sm.m_run[r];
            float mx = m_old;
            #pragma unroll
            for (int c = 0; c < 16; c++) mx = fmaxf(mx, sm.Ps[r][q + 4 * c]);
            mx = fmaxf(mx, __shfl_xor_sync(0xffffffffu, mx, 1));
            mx = fmaxf(mx, __shfl_xor_sync(0xffffffffu, mx, 2));
            float sum = 0.f;
            #pragma unroll
            for (int c = 0; c < 16; c++) {
                float p = __expf(sm.Ps[r][q + 4 * c] - mx);
                sm.Ps[r][q + 4 * c] = p;
                sum += p;
            }
            sum += __shfl_xor_sync(0xffffffffu, sum, 1);
            sum += __shfl_xor_sync(0xffffffffu, sum, 2);
            if (q == 0) {
                float al = __expf(m_old - mx);
                sm.l_run[r] = sm.l_run[r] * al + sum;
                sm.m_run[r] = mx;
                sm.alphas[r] = al;
            }
        }
        __syncthreads();

        // Rescale accumulator, then O += P @ V
        float al[4];
        #pragma unroll
        for (int i = 0; i < 4; i++) al[i] = sm.alphas[ty * 4 + i];
        #pragma unroll
        for (int i = 0; i < 4; i++)
            #pragma unroll
            for (int j = 0; j < 4; j++)
                o[i][j] *= al[i];

        #pragma unroll 8
        for (int kk = 0; kk < 64; kk++) {
            float4 b4 = *(const float4*)&sm.Vs[kk][tx * 4];
            float br_[4] = {b4.x, b4.y, b4.z, b4.w};
            float ar_[4];
            #pragma unroll
            for (int i = 0; i < 4; i++) ar_[i] = sm.Ps[ty * 4 + i][kk];
            #pragma unroll
            for (int i = 0; i < 4; i++)
                #pragma unroll
                for (int j = 0; j < 4; j++)
                    o[i][j] += ar_[i] * br_[j];
        }
    }

    // Normalize and write back into [B*S, H*DH] layout
    #pragma unroll
    for (int i = 0; i < 4; i++) {
        float inv = 1.f / sm.l_run[ty * 4 + i];
        float4 v = make_float4(o[i][0] * inv, o[i][1] * inv, o[i][2] * inv, o[i][3] * inv);
        *(float4*)&O[base + (size_t)(q0 + ty * 4 + i) * DMODEL + tx * 4] = v;
    }
}

// ---------------------------------------------------------------------------
// Launch: 3 GEMMs (Q,K,V) -> RoPE -> flash attention -> output GEMM.
// ---------------------------------------------------------------------------
extern "C" void kernel_launch(void* const* d_in, const int* in_sizes, int n_in,
                              void* d_out, int out_size) {
    const int*   positions = (const int*)d_in[0];
    const float* X  = (const float*)d_in[1];
    const float* wq = (const float*)d_in[2];
    const float* wk = (const float*)d_in[3];
    const float* wv = (const float*)d_in[4];
    const float* wo = (const float*)d_in[5];
    float* out = (float*)d_out;

    float* bufs = nullptr;
    cudaGetSymbolAddress((void**)&bufs, g_bufs);
    float* Qp = bufs;
    float* Kp = bufs + NB_ELEM;
    float* Vp = bufs + 2 * NB_ELEM;
    float* Op = bufs + 3 * NB_ELEM;

    dim3 ggrid(DMODEL / GBN, MROWS / GBM);   // (8, 64)
    gemm_tf32<<<ggrid, 256>>>(X, wq, Qp, MROWS, DMODEL, DMODEL);
    gemm_tf32<<<ggrid, 256>>>(X, wk, Kp, MROWS, DMODEL, DMODEL);
    gemm_tf32<<<ggrid, 256>>>(X, wv, Vp, MROWS, DMODEL, DMODEL);

    int pairs = MROWS * NHEADS * 32;
    rope_kernel<<<(pairs + 255) / 256, 256>>>(Qp, Kp, positions);

    int smem_bytes = (int)sizeof(AttnSmem);
    cudaFuncSetAttribute(attn_kernel, cudaFuncAttributeMaxDynamicSharedMemorySize, smem_bytes);
    attn_kernel<<<dim3(SEQ / 64, BATCH * NHEADS), 256, smem_bytes>>>(Qp, Kp, Vp, Op);

    gemm_tf32<<<ggrid, 256>>>(Op, wo, out, MROWS, DMODEL, DMODEL);
}

// round 4
// speedup vs baseline: 1.9437x; 1.2450x over previous
#include <cuda_runtime.h>
#include <cuda_bf16.h>
#include <math.h>
#include <stdint.h>

// Problem constants
#define BATCH   4
#define SEQ     2048
#define DMODEL  1024
#define NHEADS  16
#define DHEAD   64
#define MROWS   (BATCH * SEQ)            // 8192
#define NB_ELEM ((size_t)MROWS * DMODEL)

__device__ float g_bufs[4][MROWS * DMODEL];

// ---------------------------------------------------------------------------
// Helpers
// ---------------------------------------------------------------------------
__device__ __forceinline__ float to_tf32(float x) {
    float r; asm("cvt.rna.tf32.f32 %0, %1;" : "=f"(r) : "f"(x)); return r;
}
__device__ __forceinline__ void split_bf16(float x, __nv_bfloat16& h, __nv_bfloat16& l) {
    h = __float2bfloat16_rn(x);
    l = __float2bfloat16_rn(x - __bfloat162float(h));
}
__device__ __forceinline__ uint32_t pack2(__nv_bfloat16 a, __nv_bfloat16 b) {
    __nv_bfloat162 t = __halves2bfloat162(a, b);
    return *reinterpret_cast<uint32_t*>(&t);
}
__device__ __forceinline__ void mma_bf16(float* c, const uint32_t* a, const uint32_t* b) {
    asm volatile(
        "mma.sync.aligned.m16n8k16.row.col.f32.bf16.bf16.f32 "
        "{%0,%1,%2,%3}, {%4,%5,%6,%7}, {%8,%9}, {%0,%1,%2,%3};"
        : "+f"(c[0]), "+f"(c[1]), "+f"(c[2]), "+f"(c[3])
        : "r"(a[0]), "r"(a[1]), "r"(a[2]), "r"(a[3]), "r"(b[0]), "r"(b[1]));
}
__device__ __forceinline__ void mma_tf32(float* c, const float* a, const float* b) {
    unsigned const* au = reinterpret_cast<unsigned const*>(a);
    unsigned const* bu = reinterpret_cast<unsigned const*>(b);
    asm volatile(
        "mma.sync.aligned.m16n8k8.row.col.f32.tf32.tf32.f32 "
        "{%0,%1,%2,%3}, {%4,%5,%6,%7}, {%8,%9}, {%0,%1,%2,%3};"
        : "+f"(c[0]), "+f"(c[1]), "+f"(c[2]), "+f"(c[3])
        : "r"(au[0]), "r"(au[1]), "r"(au[2]), "r"(au[3]),
          "r"(bu[0]), "r"(bu[1]));
}

// ---------------------------------------------------------------------------
// bf16x3-split tensor-core GEMM: C[M,N] = A[M,K]*B[K,N], fp32 in/out.
// CTA tile 128x128, BK=32, 256 threads (8 warps: 4m x 2n, warp tile 32x64).
// smem: A tiles [m][k] and B tiles [n][k], bf16 hi/lo, row stride 44 halves.
// Double-buffered, register-prefetched.
// ---------------------------------------------------------------------------
#define RS   44                      // row stride (halves)
#define TSZ  (128 * RS * 2)          // one tile buffer bytes (11264)
#define SSTG (4 * TSZ)               // per-stage bytes (AH, AL, BH, BL)
#define GSMEM (2 * SSTG)             // 90112

__global__ __launch_bounds__(256)
void gemm_bf16x3(const float* __restrict__ A, const float* __restrict__ B,
                 float* __restrict__ C, int M, int N, int K) {
    extern __shared__ char smem[];

    const int tid  = threadIdx.x;
    const int lane = tid & 31;
    const int wid  = tid >> 5;
    const int wm   = wid & 3;               // m offset 32*wm
    const int wn   = wid >> 2;              // n offset 64*wn
    const int g    = lane >> 2;
    const int tg   = lane & 3;
    const int row0 = blockIdx.y * 128;
    const int col0 = blockIdx.x * 128;

    // global load mappings
    const int am = tid >> 1;                // 0..127
    const int ak = (tid & 1) * 16;          // 0 or 16
    const int bn = tid & 127;               // 0..127
    const int bk = (tid >> 7) * 16;         // 0 or 16

    float acc[2][8][4];
    #pragma unroll
    for (int i = 0; i < 2; i++)
        #pragma unroll
        for (int j = 0; j < 8; j++)
            #pragma unroll
            for (int q = 0; q < 4; q++) acc[i][j][q] = 0.f;

    float4 pa[4];
    float  pb[16];

    auto fetch = [&](int kc) {
        #pragma unroll
        for (int j = 0; j < 4; j++)
            pa[j] = *(const float4*)&A[(size_t)(row0 + am) * K + kc + ak + j * 4];
        #pragma unroll
        for (int j = 0; j < 16; j++)
            pb[j] = B[(size_t)(kc + bk + j) * N + col0 + bn];
    };
    auto stage_store = [&](int st) {
        __nv_bfloat16* ah = (__nv_bfloat16*)(smem + st * SSTG);
        __nv_bfloat16* al = (__nv_bfloat16*)(smem + st * SSTG + TSZ);
        __nv_bfloat16* bh = (__nv_bfloat16*)(smem + st * SSTG + 2 * TSZ);
        __nv_bfloat16* bl = (__nv_bfloat16*)(smem + st * SSTG + 3 * TSZ);
        #pragma unroll
        for (int j = 0; j < 4; j++) {
            __nv_bfloat16 h0,h1,h2,h3,l0,l1,l2,l3;
            split_bf16(pa[j].x, h0, l0); split_bf16(pa[j].y, h1, l1);
            split_bf16(pa[j].z, h2, l2); split_bf16(pa[j].w, h3, l3);
            int off = am * RS + ak + j * 4;
            *(uint2*)&ah[off] = make_uint2(pack2(h0,h1), pack2(h2,h3));
            *(uint2*)&al[off] = make_uint2(pack2(l0,l1), pack2(l2,l3));
        }
        #pragma unroll
        for (int j4 = 0; j4 < 4; j4++) {
            __nv_bfloat16 h[4], l[4];
            #pragma unroll
            for (int i = 0; i < 4; i++) split_bf16(pb[j4 * 4 + i], h[i], l[i]);
            int off = bn * RS + bk + j4 * 4;
            *(uint2*)&bh[off] = make_uint2(pack2(h[0],h[1]), pack2(h[2],h[3]));
            *(uint2*)&bl[off] = make_uint2(pack2(l[0],l[1]), pack2(l[2],l[3]));
        }
    };

    fetch(0);
    stage_store(0);
    __syncthreads();

    const int iters = K / 32;
    for (int it = 0; it < iters; it++) {
        const int cur = it & 1;
        if (it + 1 < iters) fetch((it + 1) * 32);

        const __nv_bfloat16* ah = (const __nv_bfloat16*)(smem + cur * SSTG);
        const __nv_bfloat16* al = (const __nv_bfloat16*)(smem + cur * SSTG + TSZ);
        const __nv_bfloat16* bh = (const __nv_bfloat16*)(smem + cur * SSTG + 2 * TSZ);
        const __nv_bfloat16* bl = (const __nv_bfloat16*)(smem + cur * SSTG + 3 * TSZ);

        #pragma unroll
        for (int ks = 0; ks < 32; ks += 16) {
            uint32_t fah[2][4], fal[2][4];
            #pragma unroll
            for (int mi = 0; mi < 2; mi++) {
                int mb = wm * 32 + mi * 16;
                int r0 = (mb + g) * RS + ks + 2 * tg;
                int r1 = (mb + g + 8) * RS + ks + 2 * tg;
                fah[mi][0] = *(const uint32_t*)&ah[r0];
                fah[mi][1] = *(const uint32_t*)&ah[r1];
                fah[mi][2] = *(const uint32_t*)&ah[r0 + 8];
                fah[mi][3] = *(const uint32_t*)&ah[r1 + 8];
                fal[mi][0] = *(const uint32_t*)&al[r0];
                fal[mi][1] = *(const uint32_t*)&al[r1];
                fal[mi][2] = *(const uint32_t*)&al[r0 + 8];
                fal[mi][3] = *(const uint32_t*)&al[r1 + 8];
            }
            #pragma unroll
            for (int ni = 0; ni < 8; ni++) {
                int nb = wn * 64 + ni * 8;
                int c0 = (nb + g) * RS + ks + 2 * tg;
                uint32_t fbh[2], fbl[2];
                fbh[0] = *(const uint32_t*)&bh[c0];
                fbh[1] = *(const uint32_t*)&bh[c0 + 8];
                fbl[0] = *(const uint32_t*)&bl[c0];
                fbl[1] = *(const uint32_t*)&bl[c0 + 8];
                #pragma unroll
                for (int mi = 0; mi < 2; mi++) {
                    mma_bf16(acc[mi][ni], fah[mi], fbh);   // hi*hi
                    mma_bf16(acc[mi][ni], fah[mi], fbl);   // hi*lo
                    mma_bf16(acc[mi][ni], fal[mi], fbh);   // lo*hi
                }
            }
        }

        if (it + 1 < iters) stage_store(cur ^ 1);
        __syncthreads();
    }

    // epilogue
    #pragma unroll
    for (int mi = 0; mi < 2; mi++) {
        #pragma unroll
        for (int ni = 0; ni < 8; ni++) {
            int rg = row0 + wm * 32 + mi * 16 + g;
            int cg = col0 + wn * 64 + ni * 8 + tg * 2;
            *(float2*)&C[(size_t)rg * N + cg]       = make_float2(acc[mi][ni][0], acc[mi][ni][1]);
            *(float2*)&C[(size_t)(rg + 8) * N + cg] = make_float2(acc[mi][ni][2], acc[mi][ni][3]);
        }
    }
}

// ---------------------------------------------------------------------------
// In-place NeoX RoPE on Q and K
// ---------------------------------------------------------------------------
__global__ void rope_kernel(float* __restrict__ Q, float* __restrict__ K,
                            const int* __restrict__ positions) {
    int idx = blockIdx.x * blockDim.x + threadIdx.x;
    if (idx >= MROWS * NHEADS * 32) return;
    int d = idx & 31;
    int h = (idx >> 5) & 15;
    int m = idx >> 9;
    int s = m & (SEQ - 1);

    float pos = (float)positions[s];
    float inv_freq = exp2f((float)d * -0.4152410118609203f);
    float ang = pos * inv_freq;
    float c, sn;
    sincosf(ang, &sn, &c);

    size_t base = (size_t)m * DMODEL + h * DHEAD + d;
    float q1 = Q[base], q2 = Q[base + 32];
    Q[base]      = q1 * c - q2 * sn;
    Q[base + 32] = q2 * c + q1 * sn;
    float k1 = K[base], k2 = K[base + 32];
    K[base]      = k1 * c - k2 * sn;
    K[base + 32] = k2 * c + k1 * sn;
}

// ---------------------------------------------------------------------------
// Flash attention with mma.sync tf32 for QK^T and PV.
// grid: (S/64, B*H). 256 threads (8 warps: 2m x 4n, warp tile 32x16).
// ---------------------------------------------------------------------------
struct AttnSmem {
    float Qt[64][68];   // [d][q]
    float Kt[64][68];   // [d][k]
    float Vs[64][68];   // [k][d]
    float Ps[64][68];   // [q][k]
    float m_run[64];
    float l_run[64];
    float alphas[64];
};

__global__ __launch_bounds__(256)
void attn_kernel(const float* __restrict__ Q, const float* __restrict__ K,
                 const float* __restrict__ V, float* __restrict__ O) {
    extern __shared__ char smem_raw[];
    AttnSmem& sm = *reinterpret_cast<AttnSmem*>(smem_raw);

    const int tid = threadIdx.x;
    const int lane = tid & 31;
    const int wid = tid >> 5;
    const int g = lane >> 2;
    const int tg = lane & 3;
    const int m0 = (wid & 1) * 32;
    const int n0 = (wid >> 1) * 16;

    const int bh = blockIdx.y;
    const int b = bh >> 4;
    const int h = bh & 15;
    const int q0 = blockIdx.x * 64;
    const size_t base = (size_t)b * SEQ * DMODEL + (size_t)h * DHEAD;

    // Load Q tile transposed (tf32-rounded)
    {
        const int lr = tid >> 4;
        const int d4 = (tid & 15) * 4;
        #pragma unroll
        for (int i = 0; i < 4; i++) {
            int r = lr + i * 16;
            float4 qv = *(const float4*)&Q[base + (size_t)(q0 + r) * DMODEL + d4];
            sm.Qt[d4 + 0][r] = to_tf32(qv.x);
            sm.Qt[d4 + 1][r] = to_tf32(qv.y);
            sm.Qt[d4 + 2][r] = to_tf32(qv.z);
            sm.Qt[d4 + 3][r] = to_tf32(qv.w);
        }
    }
    if (tid < 64) { sm.m_run[tid] = -INFINITY; sm.l_run[tid] = 0.f; }

    float accO[2][2][4] = {};

    for (int kt = 0; kt < SEQ; kt += 64) {
        __syncthreads();
        {
            const int lr = tid >> 4;
            const int d4 = (tid & 15) * 4;
            #pragma unroll
            for (int i = 0; i < 4; i++) {
                int r = lr + i * 16;
                float4 kv = *(const float4*)&K[base + (size_t)(kt + r) * DMODEL + d4];
                sm.Kt[d4 + 0][r] = to_tf32(kv.x);
                sm.Kt[d4 + 1][r] = to_tf32(kv.y);
                sm.Kt[d4 + 2][r] = to_tf32(kv.z);
                sm.Kt[d4 + 3][r] = to_tf32(kv.w);
                float4 vv = *(const float4*)&V[base + (size_t)(kt + r) * DMODEL + d4];
                vv.x = to_tf32(vv.x); vv.y = to_tf32(vv.y);
                vv.z = to_tf32(vv.z); vv.w = to_tf32(vv.w);
                *(float4*)&sm.Vs[r][d4] = vv;
            }
        }
        __syncthreads();

        // S = Q K^T via tf32 MMA
        float sf[2][2][4] = {};
        #pragma unroll
        for (int ks = 0; ks < 64; ks += 8) {
            float a[2][4], bb[2][2];
            #pragma unroll
            for (int mi = 0; mi < 2; mi++) {
                int mb = m0 + mi * 16;
                a[mi][0] = sm.Qt[ks + tg][mb + g];
                a[mi][1] = sm.Qt[ks + tg][mb + g + 8];
                a[mi][2] = sm.Qt[ks + 4 + tg][mb + g];
                a[mi][3] = sm.Qt[ks + 4 + tg][mb + g + 8];
            }
            #pragma unroll
            for (int ni = 0; ni < 2; ni++) {
                int nb = n0 + ni * 8;
                bb[ni][0] = sm.Kt[ks + tg][nb + g];
                bb[ni][1] = sm.Kt[ks + 4 + tg][nb + g];
            }
            #pragma unroll
            for (int mi = 0; mi < 2; mi++)
                #pragma unroll
                for (int ni = 0; ni < 2; ni++)
                    mma_tf32(sf[mi][ni], a[mi], bb[ni]);
        }
        #pragma unroll
        for (int mi = 0; mi < 2; mi++)
            #pragma unroll
            for (int ni = 0; ni < 2; ni++) {
                int r = m0 + mi * 16 + g;
                int c = n0 + ni * 8 + tg * 2;
                *(float2*)&sm.Ps[r][c]     = make_float2(sf[mi][ni][0], sf[mi][ni][1]);
                *(float2*)&sm.Ps[r + 8][c] = make_float2(sf[mi][ni][2], sf[mi][ni][3]);
            }
        __syncthreads();

        // Online softmax: 4 threads per row
        {
            const int r = tid >> 2;
            const int q = tid & 3;
            float m_old = sm.m_run[r];
            float mx = m_old;
            #pragma unroll
            for (int c = 0; c < 16; c++) mx = fmaxf(mx, sm.Ps[r][q + 4 * c]);
            mx = fmaxf(mx, __shfl_xor_sync(0xffffffffu, mx, 1));
            mx = fmaxf(mx, __shfl_xor_sync(0xffffffffu, mx, 2));
            float sum = 0.f;
            #pragma unroll
            for (int c = 0; c < 16; c++) {
                float p = to_tf32(__expf(sm.Ps[r][q + 4 * c] - mx));
                sm.Ps[r][q + 4 * c] = p;
                sum += p;
            }
            sum += __shfl_xor_sync(0xffffffffu, sum, 1);
            sum += __shfl_xor_sync(0xffffffffu, sum, 2);
            if (q == 0) {
                float al = __expf(m_old - mx);
                sm.l_run[r] = sm.l_run[r] * al + sum;
                sm.m_run[r] = mx;
                sm.alphas[r] = al;
            }
        }
        __syncthreads();

        // Rescale accumulators
        #pragma unroll
        for (int mi = 0; mi < 2; mi++) {
            float al0 = sm.alphas[m0 + mi * 16 + g];
            float al1 = sm.alphas[m0 + mi * 16 + g + 8];
            #pragma unroll
            for (int ni = 0; ni < 2; ni++) {
                accO[mi][ni][0] *= al0; accO[mi][ni][1] *= al0;
                accO[mi][ni][2] *= al1; accO[mi][ni][3] *= al1;
            }
        }
        // O += P @ V via tf32 MMA
        #pragma unroll
        for (int ks = 0; ks < 64; ks += 8) {
            float a[2][4], bb[2][2];
            #pragma unroll
            for (int mi = 0; mi < 2; mi++) {
                int r = m0 + mi * 16 + g;
                a[mi][0] = sm.Ps[r][ks + tg];
                a[mi][1] = sm.Ps[r + 8][ks + tg];
                a[mi][2] = sm.Ps[r][ks + tg + 4];
                a[mi][3] = sm.Ps[r + 8][ks + tg + 4];
            }
            #pragma unroll
            for (int ni = 0; ni < 2; ni++) {
                int nb = n0 + ni * 8;
                bb[ni][0] = sm.Vs[ks + tg][nb + g];
                bb[ni][1] = sm.Vs[ks + 4 + tg][nb + g];
            }
            #pragma unroll
            for (int mi = 0; mi < 2; mi++)
                #pragma unroll
                for (int ni = 0; ni < 2; ni++)
                    mma_tf32(accO[mi][ni], a[mi], bb[ni]);
        }
    }

    // Final normalize + store
    #pragma unroll
    for (int mi = 0; mi < 2; mi++) {
        int r = m0 + mi * 16 + g;
        float i0 = 1.f / sm.l_run[r];
        float i1 = 1.f / sm.l_run[r + 8];
        #pragma unroll
        for (int ni = 0; ni < 2; ni++) {
            int c = n0 + ni * 8 + tg * 2;
            *(float2*)&O[base + (size_t)(q0 + r) * DMODEL + c] =
                make_float2(accO[mi][ni][0] * i0, accO[mi][ni][1] * i0);
            *(float2*)&O[base + (size_t)(q0 + r + 8) * DMODEL + c] =
                make_float2(accO[mi][ni][2] * i1, accO[mi][ni][3] * i1);
        }
    }
}

// ---------------------------------------------------------------------------
// Launch
// ---------------------------------------------------------------------------
extern "C" void kernel_launch(void* const* d_in, const int* in_sizes, int n_in,
                              void* d_out, int out_size) {
    const int*   positions = (const int*)d_in[0];
    const float* X  = (const float*)d_in[1];
    const float* wq = (const float*)d_in[2];
    const float* wk = (const float*)d_in[3];
    const float* wv = (const float*)d_in[4];
    const float* wo = (const float*)d_in[5];
    float* out = (float*)d_out;

    float* bufs = nullptr;
    cudaGetSymbolAddress((void**)&bufs, g_bufs);
    float* Qp = bufs;
    float* Kp = bufs + NB_ELEM;
    float* Vp = bufs + 2 * NB_ELEM;
    float* Op = bufs + 3 * NB_ELEM;

    cudaFuncSetAttribute(gemm_bf16x3, cudaFuncAttributeMaxDynamicSharedMemorySize, GSMEM);
    dim3 ggrid(DMODEL / 128, MROWS / 128);   // (8, 64)
    gemm_bf16x3<<<ggrid, 256, GSMEM>>>(X, wq, Qp, MROWS, DMODEL, DMODEL);
    gemm_bf16x3<<<ggrid, 256, GSMEM>>>(X, wk, Kp, MROWS, DMODEL, DMODEL);
    gemm_bf16x3<<<ggrid, 256, GSMEM>>>(X, wv, Vp, MROWS, DMODEL, DMODEL);

    int pairs = MROWS * NHEADS * 32;
    rope_kernel<<<(pairs + 255) / 256, 256>>>(Qp, Kp, positions);

    int smem_bytes = (int)sizeof(AttnSmem);
    cudaFuncSetAttribute(attn_kernel, cudaFuncAttributeMaxDynamicSharedMemorySize, smem_bytes);
    attn_kernel<<<dim3(SEQ / 64, BATCH * NHEADS), 256, smem_bytes>>>(Qp, Kp, Vp, Op);

    gemm_bf16x3<<<ggrid, 256, GSMEM>>>(Op, wo, out, MROWS, DMODEL, DMODEL);
}

// round 5
// speedup vs baseline: 1.9834x; 1.0204x over previous
#include <cuda_runtime.h>
#include <cuda_bf16.h>
#include <math.h>
#include <stdint.h>

// Problem constants
#define BATCH   4
#define SEQ     2048
#define DMODEL  1024
#define NHEADS  16
#define DHEAD   64
#define MROWS   (BATCH * SEQ)            // 8192
#define NB_ELEM ((size_t)MROWS * DMODEL)

// fp32 scratch: Q, K, V projections + attention output
__device__ float g_bufs[4][MROWS * DMODEL];
// bf16 hi/lo pre-split buffers
__device__ __nv_bfloat16 g_xh[MROWS * DMODEL];
__device__ __nv_bfloat16 g_xl[MROWS * DMODEL];
__device__ __nv_bfloat16 g_oh[MROWS * DMODEL];
__device__ __nv_bfloat16 g_ol[MROWS * DMODEL];
__device__ __nv_bfloat16 g_wht[4][DMODEL * DMODEL];  // transposed [n][k]
__device__ __nv_bfloat16 g_wlt[4][DMODEL * DMODEL];

// ---------------------------------------------------------------------------
// Helpers
// ---------------------------------------------------------------------------
__device__ __forceinline__ float to_tf32(float x) {
    float r; asm("cvt.rna.tf32.f32 %0, %1;" : "=f"(r) : "f"(x)); return r;
}
__device__ __forceinline__ void split_bf16(float x, __nv_bfloat16& h, __nv_bfloat16& l) {
    h = __float2bfloat16_rn(x);
    l = __float2bfloat16_rn(x - __bfloat162float(h));
}
__device__ __forceinline__ uint32_t pack2(__nv_bfloat16 a, __nv_bfloat16 b) {
    __nv_bfloat162 t = __halves2bfloat162(a, b);
    return *reinterpret_cast<uint32_t*>(&t);
}
__device__ __forceinline__ void mma_bf16(float* c, const uint32_t* a, const uint32_t* b) {
    asm volatile(
        "mma.sync.aligned.m16n8k16.row.col.f32.bf16.bf16.f32 "
        "{%0,%1,%2,%3}, {%4,%5,%6,%7}, {%8,%9}, {%0,%1,%2,%3};"
        : "+f"(c[0]), "+f"(c[1]), "+f"(c[2]), "+f"(c[3])
        : "r"(a[0]), "r"(a[1]), "r"(a[2]), "r"(a[3]), "r"(b[0]), "r"(b[1]));
}
__device__ __forceinline__ void mma_tf32(float* c, const float* a, const float* b) {
    unsigned const* au = reinterpret_cast<unsigned const*>(a);
    unsigned const* bu = reinterpret_cast<unsigned const*>(b);
    asm volatile(
        "mma.sync.aligned.m16n8k8.row.col.f32.tf32.tf32.f32 "
        "{%0,%1,%2,%3}, {%4,%5,%6,%7}, {%8,%9}, {%0,%1,%2,%3};"
        : "+f"(c[0]), "+f"(c[1]), "+f"(c[2]), "+f"(c[3])
        : "r"(au[0]), "r"(au[1]), "r"(au[2]), "r"(au[3]),
          "r"(bu[0]), "r"(bu[1]));
}

// ---------------------------------------------------------------------------
// Split fp32 -> bf16 hi/lo (same layout)
// ---------------------------------------------------------------------------
__global__ void split_plain(const float* __restrict__ X,
                            __nv_bfloat16* __restrict__ H,
                            __nv_bfloat16* __restrict__ L, int n4) {
    int i = blockIdx.x * blockDim.x + threadIdx.x;
    if (i >= n4) return;
    float4 v = ((const float4*)X)[i];
    __nv_bfloat16 h0,h1,h2,h3,l0,l1,l2,l3;
    split_bf16(v.x, h0, l0); split_bf16(v.y, h1, l1);
    split_bf16(v.z, h2, l2); split_bf16(v.w, h3, l3);
    ((uint2*)H)[i] = make_uint2(pack2(h0,h1), pack2(h2,h3));
    ((uint2*)L)[i] = make_uint2(pack2(l0,l1), pack2(l2,l3));
}

// ---------------------------------------------------------------------------
// Split + transpose weights: W[k][n] (1024x1024) -> Ht[n][k], Lt[n][k]
// ---------------------------------------------------------------------------
__global__ void split_wt(const float* __restrict__ W,
                         __nv_bfloat16* __restrict__ Ht,
                         __nv_bfloat16* __restrict__ Lt) {
    __shared__ float t[32][33];
    const int n0 = blockIdx.x * 32, k0 = blockIdx.y * 32;
    const int tx = threadIdx.x, ty = threadIdx.y;
    #pragma unroll
    for (int i = 0; i < 4; i++)
        t[ty + 8 * i][tx] = W[(size_t)(k0 + ty + 8 * i) * DMODEL + n0 + tx];
    __syncthreads();
    #pragma unroll
    for (int i = 0; i < 4; i++) {
        float v = t[tx][ty + 8 * i];
        __nv_bfloat16 h, l;
        split_bf16(v, h, l);
        size_t o = (size_t)(n0 + ty + 8 * i) * DMODEL + k0 + tx;
        Ht[o] = h;
        Lt[o] = l;
    }
}

// ---------------------------------------------------------------------------
// bf16x3-split tensor-core GEMM on pre-split operands.
// C[M,N] = A[M,K]*B[K,N]; A given as AH/AL [m][k] bf16; B as BHt/BLt [n][k].
// CTA tile 128x128, BK=32, 256 threads (8 warps: 4m x 2n, warp tile 32x64).
// ---------------------------------------------------------------------------
#define RS   44                      // smem row stride (halves)
#define TSZ  (128 * RS * 2)          // one tile buffer bytes (11264)
#define SSTG (4 * TSZ)               // per-stage bytes (AH, AL, BH, BL)
#define GSMEM (2 * SSTG)             // 90112

__global__ __launch_bounds__(256)
void gemm_bf16s(const __nv_bfloat16* __restrict__ AH, const __nv_bfloat16* __restrict__ AL,
                const __nv_bfloat16* __restrict__ BHt, const __nv_bfloat16* __restrict__ BLt,
                float* __restrict__ C, int M, int N, int K) {
    extern __shared__ char smem[];

    const int tid  = threadIdx.x;
    const int lane = tid & 31;
    const int wid  = tid >> 5;
    const int wm   = wid & 3;
    const int wn   = wid >> 2;
    const int g    = lane >> 2;
    const int tg   = lane & 3;
    const int row0 = blockIdx.y * 128;
    const int col0 = blockIdx.x * 128;

    const int am = tid >> 1;                // 0..127
    const int ak = (tid & 1) * 16;          // 0 or 16
    const int bn = tid & 127;
    const int bk = (tid >> 7) * 16;

    float acc[2][8][4];
    #pragma unroll
    for (int i = 0; i < 2; i++)
        #pragma unroll
        for (int j = 0; j < 8; j++)
            #pragma unroll
            for (int q = 0; q < 4; q++) acc[i][j][q] = 0.f;

    uint4 ph[2], pl[2], qh[2], ql[2];

    auto fetch = [&](int kc) {
        size_t ab = (size_t)(row0 + am) * K + kc + ak;
        ph[0] = *(const uint4*)&AH[ab];      ph[1] = *(const uint4*)&AH[ab + 8];
        pl[0] = *(const uint4*)&AL[ab];      pl[1] = *(const uint4*)&AL[ab + 8];
        size_t bb = (size_t)(col0 + bn) * K + kc + bk;
        qh[0] = *(const uint4*)&BHt[bb];     qh[1] = *(const uint4*)&BHt[bb + 8];
        ql[0] = *(const uint4*)&BLt[bb];     ql[1] = *(const uint4*)&BLt[bb + 8];
    };
    auto st4 = [&](__nv_bfloat16* p, int off, const uint4& a, const uint4& b) {
        *(uint2*)&p[off]      = make_uint2(a.x, a.y);
        *(uint2*)&p[off + 4]  = make_uint2(a.z, a.w);
        *(uint2*)&p[off + 8]  = make_uint2(b.x, b.y);
        *(uint2*)&p[off + 12] = make_uint2(b.z, b.w);
    };
    auto stage_store = [&](int st) {
        __nv_bfloat16* ah = (__nv_bfloat16*)(smem + st * SSTG);
        __nv_bfloat16* al = (__nv_bfloat16*)(smem + st * SSTG + TSZ);
        __nv_bfloat16* bh = (__nv_bfloat16*)(smem + st * SSTG + 2 * TSZ);
        __nv_bfloat16* bl = (__nv_bfloat16*)(smem + st * SSTG + 3 * TSZ);
        st4(ah, am * RS + ak, ph[0], ph[1]);
        st4(al, am * RS + ak, pl[0], pl[1]);
        st4(bh, bn * RS + bk, qh[0], qh[1]);
        st4(bl, bn * RS + bk, ql[0], ql[1]);
    };

    fetch(0);
    stage_store(0);
    __syncthreads();

    const int iters = K / 32;
    for (int it = 0; it < iters; it++) {
        const int cur = it & 1;
        if (it + 1 < iters) fetch((it + 1) * 32);

        const __nv_bfloat16* ah = (const __nv_bfloat16*)(smem + cur * SSTG);
        const __nv_bfloat16* al = (const __nv_bfloat16*)(smem + cur * SSTG + TSZ);
        const __nv_bfloat16* bh = (const __nv_bfloat16*)(smem + cur * SSTG + 2 * TSZ);
        const __nv_bfloat16* bl = (const __nv_bfloat16*)(smem + cur * SSTG + 3 * TSZ);

        #pragma unroll
        for (int ks = 0; ks < 32; ks += 16) {
            uint32_t fah[2][4], fal[2][4];
            #pragma unroll
            for (int mi = 0; mi < 2; mi++) {
                int mb = wm * 32 + mi * 16;
                int r0 = (mb + g) * RS + ks + 2 * tg;
                int r1 = (mb + g + 8) * RS + ks + 2 * tg;
                fah[mi][0] = *(const uint32_t*)&ah[r0];
                fah[mi][1] = *(const uint32_t*)&ah[r1];
                fah[mi][2] = *(const uint32_t*)&ah[r0 + 8];
                fah[mi][3] = *(const uint32_t*)&ah[r1 + 8];
                fal[mi][0] = *(const uint32_t*)&al[r0];
                fal[mi][1] = *(const uint32_t*)&al[r1];
                fal[mi][2] = *(const uint32_t*)&al[r0 + 8];
                fal[mi][3] = *(const uint32_t*)&al[r1 + 8];
            }
            #pragma unroll
            for (int ni = 0; ni < 8; ni++) {
                int nb = wn * 64 + ni * 8;
                int c0 = (nb + g) * RS + ks + 2 * tg;
                uint32_t fbh[2], fbl[2];
                fbh[0] = *(const uint32_t*)&bh[c0];
                fbh[1] = *(const uint32_t*)&bh[c0 + 8];
                fbl[0] = *(const uint32_t*)&bl[c0];
                fbl[1] = *(const uint32_t*)&bl[c0 + 8];
                #pragma unroll
                for (int mi = 0; mi < 2; mi++) {
                    mma_bf16(acc[mi][ni], fah[mi], fbh);   // hi*hi
                    mma_bf16(acc[mi][ni], fah[mi], fbl);   // hi*lo
                    mma_bf16(acc[mi][ni], fal[mi], fbh);   // lo*hi
                }
            }
        }

        if (it + 1 < iters) stage_store(cur ^ 1);
        __syncthreads();
    }

    #pragma unroll
    for (int mi = 0; mi < 2; mi++) {
        #pragma unroll
        for (int ni = 0; ni < 8; ni++) {
            int rg = row0 + wm * 32 + mi * 16 + g;
            int cg = col0 + wn * 64 + ni * 8 + tg * 2;
            *(float2*)&C[(size_t)rg * N + cg]       = make_float2(acc[mi][ni][0], acc[mi][ni][1]);
            *(float2*)&C[(size_t)(rg + 8) * N + cg] = make_float2(acc[mi][ni][2], acc[mi][ni][3]);
        }
    }
}

// ---------------------------------------------------------------------------
// In-place NeoX RoPE on Q and K
// ---------------------------------------------------------------------------
__global__ void rope_kernel(float* __restrict__ Q, float* __restrict__ K,
                            const int* __restrict__ positions) {
    int idx = blockIdx.x * blockDim.x + threadIdx.x;
    if (idx >= MROWS * NHEADS * 32) return;
    int d = idx & 31;
    int h = (idx >> 5) & 15;
    int m = idx >> 9;
    int s = m & (SEQ - 1);

    float pos = (float)positions[s];
    float inv_freq = exp2f((float)d * -0.4152410118609203f);
    float ang = pos * inv_freq;
    float c, sn;
    sincosf(ang, &sn, &c);

    size_t base = (size_t)m * DMODEL + h * DHEAD + d;
    float q1 = Q[base], q2 = Q[base + 32];
    Q[base]      = q1 * c - q2 * sn;
    Q[base + 32] = q2 * c + q1 * sn;
    float k1 = K[base], k2 = K[base + 32];
    K[base]      = k1 * c - k2 * sn;
    K[base + 32] = k2 * c + k1 * sn;
}

// ---------------------------------------------------------------------------
// Flash attention v2: BQ=128, 8 warps x m16 (full n=64 per warp), tf32 MMA.
// Q fragments register-resident; Qt smem aliased with Ps.
// grid: (SEQ/128, B*H) = (16, 64). 256 threads.
// ---------------------------------------------------------------------------
#define PS_OFF 0                      // Ps[128][68] floats (union with Qt[64][132])
#define KT_OFF 8704                   // Kt[64][68]
#define VS_OFF 13056                  // Vs[64][68]
#define MR_OFF 17408                  // m_run[128]
#define LR_OFF 17536                  // l_run[128]
#define ALP_OFF 17664                 // alphas[128]
#define ASMEM  (17792 * 4)            // 71168 bytes

__global__ __launch_bounds__(256)
void attn2_kernel(const float* __restrict__ Q, const float* __restrict__ K,
                  const float* __restrict__ V, float* __restrict__ O) {
    extern __shared__ float sf32[];
    float* Ps = sf32 + PS_OFF;        // [128][68]
    float* Qt = sf32 + PS_OFF;        // [64][132] (alias, prologue only)
    float* Kt = sf32 + KT_OFF;        // [64][68]
    float* Vs = sf32 + VS_OFF;        // [64][68]
    float* m_run  = sf32 + MR_OFF;
    float* l_run  = sf32 + LR_OFF;
    float* alphas = sf32 + ALP_OFF;

    const int tid = threadIdx.x;
    const int lane = tid & 31;
    const int wid = tid >> 5;
    const int g = lane >> 2;
    const int tg = lane & 3;
    const int m0 = wid * 16;

    const int bh = blockIdx.y;
    const int b = bh >> 4;
    const int h = bh & 15;
    const int q0 = blockIdx.x * 128;
    const size_t base = (size_t)b * SEQ * DMODEL + (size_t)h * DHEAD;

    // Prologue: Q tile (128 rows) transposed into Qt[d][q], tf32-rounded
    {
        const int lr = tid >> 4;
        const int d4 = (tid & 15) * 4;
        #pragma unroll
        for (int i = 0; i < 8; i++) {
            int r = lr + i * 16;
            float4 qv = *(const float4*)&Q[base + (size_t)(q0 + r) * DMODEL + d4];
            Qt[(d4 + 0) * 132 + r] = to_tf32(qv.x);
            Qt[(d4 + 1) * 132 + r] = to_tf32(qv.y);
            Qt[(d4 + 2) * 132 + r] = to_tf32(qv.z);
            Qt[(d4 + 3) * 132 + r] = to_tf32(qv.w);
        }
    }
    if (tid < 128) { m_run[tid] = -INFINITY; l_run[tid] = 0.f; }
    __syncthreads();

    // Hoist Q A-fragments into registers: 8 k-steps x 4
    float qa[8][4];
    #pragma unroll
    for (int kst = 0; kst < 8; kst++) {
        int ks = kst * 8;
        qa[kst][0] = Qt[(ks + tg) * 132 + m0 + g];
        qa[kst][1] = Qt[(ks + tg) * 132 + m0 + g + 8];
        qa[kst][2] = Qt[(ks + 4 + tg) * 132 + m0 + g];
        qa[kst][3] = Qt[(ks + 4 + tg) * 132 + m0 + g + 8];
    }

    float accO[8][4];
    #pragma unroll
    for (int i = 0; i < 8; i++)
        #pragma unroll
        for (int j = 0; j < 4; j++) accO[i][j] = 0.f;

    for (int kt = 0; kt < SEQ; kt += 64) {
        __syncthreads();   // Q-frag reads & prior-iter PV reads done before K/V overwrite
        {
            const int lr = tid >> 4;
            const int d4 = (tid & 15) * 4;
            #pragma unroll
            for (int i = 0; i < 4; i++) {
                int r = lr + i * 16;
                float4 kv = *(const float4*)&K[base + (size_t)(kt + r) * DMODEL + d4];
                Kt[(d4 + 0) * 68 + r] = to_tf32(kv.x);
                Kt[(d4 + 1) * 68 + r] = to_tf32(kv.y);
                Kt[(d4 + 2) * 68 + r] = to_tf32(kv.z);
                Kt[(d4 + 3) * 68 + r] = to_tf32(kv.w);
                float4 vv = *(const float4*)&V[base + (size_t)(kt + r) * DMODEL + d4];
                Vs[r * 68 + d4 + 0] = to_tf32(vv.x);
                Vs[r * 68 + d4 + 1] = to_tf32(vv.y);
                Vs[r * 68 + d4 + 2] = to_tf32(vv.z);
                Vs[r * 68 + d4 + 3] = to_tf32(vv.w);
            }
        }
        __syncthreads();

        // S = Q K^T : warp computes m16 x n64
        float s[8][4];
        #pragma unroll
        for (int i = 0; i < 8; i++)
            #pragma unroll
            for (int j = 0; j < 4; j++) s[i][j] = 0.f;
        #pragma unroll
        for (int kst = 0; kst < 8; kst++) {
            int ks = kst * 8;
            #pragma unroll
            for (int ni = 0; ni < 8; ni++) {
                int nb = ni * 8;
                float bb[2];
                bb[0] = Kt[(ks + tg) * 68 + nb + g];
                bb[1] = Kt[(ks + 4 + tg) * 68 + nb + g];
                mma_tf32(s[ni], qa[kst], bb);
            }
        }
        // write P tile
        #pragma unroll
        for (int ni = 0; ni < 8; ni++) {
            int c = ni * 8 + tg * 2;
            *(float2*)&Ps[(m0 + g) * 68 + c]     = make_float2(s[ni][0], s[ni][1]);
            *(float2*)&Ps[(m0 + g + 8) * 68 + c] = make_float2(s[ni][2], s[ni][3]);
        }
        __syncthreads();

        // Online softmax: 2 threads per row
        {
            const int r = tid >> 1;
            const int q = tid & 1;
            float m_old = m_run[r];
            float mx = m_old;
            #pragma unroll
            for (int c = 0; c < 32; c++) mx = fmaxf(mx, Ps[r * 68 + q * 32 + c]);
            mx = fmaxf(mx, __shfl_xor_sync(0xffffffffu, mx, 1));
            float sum = 0.f;
            #pragma unroll
            for (int c = 0; c < 32; c++) {
                float p = to_tf32(__expf(Ps[r * 68 + q * 32 + c] - mx));
                Ps[r * 68 + q * 32 + c] = p;
                sum += p;
            }
            sum += __shfl_xor_sync(0xffffffffu, sum, 1);
            if (q == 0) {
                float al = __expf(m_old - mx);
                l_run[r] = l_run[r] * al + sum;
                m_run[r] = mx;
                alphas[r] = al;
            }
        }
        __syncthreads();

        // Rescale accumulators
        {
            float al0 = alphas[m0 + g];
            float al1 = alphas[m0 + g + 8];
            #pragma unroll
            for (int ni = 0; ni < 8; ni++) {
                accO[ni][0] *= al0; accO[ni][1] *= al0;
                accO[ni][2] *= al1; accO[ni][3] *= al1;
            }
        }
        // O += P @ V
        #pragma unroll
        for (int kst = 0; kst < 8; kst++) {
            int ks = kst * 8;
            float a[4];
            a[0] = Ps[(m0 + g) * 68 + ks + tg];
            a[1] = Ps[(m0 + g + 8) * 68 + ks + tg];
            a[2] = Ps[(m0 + g) * 68 + ks + tg + 4];
            a[3] = Ps[(m0 + g + 8) * 68 + ks + tg + 4];
            #pragma unroll
            for (int ni = 0; ni < 8; ni++) {
                int nb = ni * 8;
                float bb[2];
                bb[0] = Vs[(ks + tg) * 68 + nb + g];
                bb[1] = Vs[(ks + 4 + tg) * 68 + nb + g];
                mma_tf32(accO[ni], a, bb);
            }
        }
    }

    // Final normalize + store
    {
        float i0 = 1.f / l_run[m0 + g];
        float i1 = 1.f / l_run[m0 + g + 8];
        #pragma unroll
        for (int ni = 0; ni < 8; ni++) {
            int c = ni * 8 + tg * 2;
            *(float2*)&O[base + (size_t)(q0 + m0 + g) * DMODEL + c] =
                make_float2(accO[ni][0] * i0, accO[ni][1] * i0);
            *(float2*)&O[base + (size_t)(q0 + m0 + g + 8) * DMODEL + c] =
                make_float2(accO[ni][2] * i1, accO[ni][3] * i1);
        }
    }
}

// ---------------------------------------------------------------------------
// Launch
// ---------------------------------------------------------------------------
extern "C" void kernel_launch(void* const* d_in, const int* in_sizes, int n_in,
                              void* d_out, int out_size) {
    const int*   positions = (const int*)d_in[0];
    const float* X  = (const float*)d_in[1];
    const float* wq = (const float*)d_in[2];
    const float* wk = (const float*)d_in[3];
    const float* wv = (const float*)d_in[4];
    const float* wo = (const float*)d_in[5];
    float* out = (float*)d_out;

    float* bufs = nullptr;
    cudaGetSymbolAddress((void**)&bufs, g_bufs);
    float* Qp = bufs;
    float* Kp = bufs + NB_ELEM;
    float* Vp = bufs + 2 * NB_ELEM;
    float* Op = bufs + 3 * NB_ELEM;

    __nv_bfloat16 *xh, *xl, *oh, *ol, *wht, *wlt;
    cudaGetSymbolAddress((void**)&xh, g_xh);
    cudaGetSymbolAddress((void**)&xl, g_xl);
    cudaGetSymbolAddress((void**)&oh, g_oh);
    cudaGetSymbolAddress((void**)&ol, g_ol);
    cudaGetSymbolAddress((void**)&wht, g_wht);
    cudaGetSymbolAddress((void**)&wlt, g_wlt);
    const size_t WSZ = (size_t)DMODEL * DMODEL;

    // Pre-split inputs and weights
    int n4 = (int)(NB_ELEM / 4);
    split_plain<<<(n4 + 255) / 256, 256>>>(X, xh, xl, n4);
    dim3 wtg(DMODEL / 32, DMODEL / 32), wtb(32, 8);
    split_wt<<<wtg, wtb>>>(wq, wht + 0 * WSZ, wlt + 0 * WSZ);
    split_wt<<<wtg, wtb>>>(wk, wht + 1 * WSZ, wlt + 1 * WSZ);
    split_wt<<<wtg, wtb>>>(wv, wht + 2 * WSZ, wlt + 2 * WSZ);
    split_wt<<<wtg, wtb>>>(wo, wht + 3 * WSZ, wlt + 3 * WSZ);

    cudaFuncSetAttribute(gemm_bf16s, cudaFuncAttributeMaxDynamicSharedMemorySize, GSMEM);
    dim3 ggrid(DMODEL / 128, MROWS / 128);   // (8, 64)
    gemm_bf16s<<<ggrid, 256, GSMEM>>>(xh, xl, wht + 0 * WSZ, wlt + 0 * WSZ, Qp, MROWS, DMODEL, DMODEL);
    gemm_bf16s<<<ggrid, 256, GSMEM>>>(xh, xl, wht + 1 * WSZ, wlt + 1 * WSZ, Kp, MROWS, DMODEL, DMODEL);
    gemm_bf16s<<<ggrid, 256, GSMEM>>>(xh, xl, wht + 2 * WSZ, wlt + 2 * WSZ, Vp, MROWS, DMODEL, DMODEL);

    int pairs = MROWS * NHEADS * 32;
    rope_kernel<<<(pairs + 255) / 256, 256>>>(Qp, Kp, positions);

    cudaFuncSetAttribute(attn2_kernel, cudaFuncAttributeMaxDynamicSharedMemorySize, ASMEM);
    attn2_kernel<<<dim3(SEQ / 128, BATCH * NHEADS), 256, ASMEM>>>(Qp, Kp, Vp, Op);

    split_plain<<<(n4 + 255) / 256, 256>>>(Op, oh, ol, n4);
    gemm_bf16s<<<ggrid, 256, GSMEM>>>(oh, ol, wht + 3 * WSZ, wlt + 3 * WSZ, out, MROWS, DMODEL, DMODEL);
}

// round 6
// speedup vs baseline: 2.3784x; 1.1992x over previous
#include <cuda_runtime.h>
#include <cuda_bf16.h>
#include <cuda_fp16.h>
#include <math.h>
#include <stdint.h>

// Problem constants
#define BATCH   4
#define SEQ     2048
#define DMODEL  1024
#define NHEADS  16
#define DHEAD   64
#define MROWS   (BATCH * SEQ)            // 8192
#define NB_ELEM ((size_t)MROWS * DMODEL)

// fp32 scratch: Q, K, V projections + attention output
__device__ float g_bufs[4][MROWS * DMODEL];
// bf16 hi/lo pre-split buffers
__device__ __nv_bfloat16 g_xh[MROWS * DMODEL];
__device__ __nv_bfloat16 g_xl[MROWS * DMODEL];
__device__ __nv_bfloat16 g_oh[MROWS * DMODEL];
__device__ __nv_bfloat16 g_ol[MROWS * DMODEL];
__device__ __nv_bfloat16 g_wht[4][DMODEL * DMODEL];  // transposed [n][k]
__device__ __nv_bfloat16 g_wlt[4][DMODEL * DMODEL];

// ---------------------------------------------------------------------------
// Helpers
// ---------------------------------------------------------------------------
__device__ __forceinline__ void split_bf16(float x, __nv_bfloat16& h, __nv_bfloat16& l) {
    h = __float2bfloat16_rn(x);
    l = __float2bfloat16_rn(x - __bfloat162float(h));
}
__device__ __forceinline__ uint32_t pack2(__nv_bfloat16 a, __nv_bfloat16 b) {
    __nv_bfloat162 t = __halves2bfloat162(a, b);
    return *reinterpret_cast<uint32_t*>(&t);
}
__device__ __forceinline__ uint32_t packh2(float a, float b) {
    __half2 t = __floats2half2_rn(a, b);
    return *reinterpret_cast<uint32_t*>(&t);
}
__device__ __forceinline__ void mma_bf16(float* c, const uint32_t* a, const uint32_t* b) {
    asm volatile(
        "mma.sync.aligned.m16n8k16.row.col.f32.bf16.bf16.f32 "
        "{%0,%1,%2,%3}, {%4,%5,%6,%7}, {%8,%9}, {%0,%1,%2,%3};"
        : "+f"(c[0]), "+f"(c[1]), "+f"(c[2]), "+f"(c[3])
        : "r"(a[0]), "r"(a[1]), "r"(a[2]), "r"(a[3]), "r"(b[0]), "r"(b[1]));
}
__device__ __forceinline__ void mma_f16(float* c, const uint32_t* a, const uint32_t* b) {
    asm volatile(
        "mma.sync.aligned.m16n8k16.row.col.f32.f16.f16.f32 "
        "{%0,%1,%2,%3}, {%4,%5,%6,%7}, {%8,%9}, {%0,%1,%2,%3};"
        : "+f"(c[0]), "+f"(c[1]), "+f"(c[2]), "+f"(c[3])
        : "r"(a[0]), "r"(a[1]), "r"(a[2]), "r"(a[3]), "r"(b[0]), "r"(b[1]));
}

// ---------------------------------------------------------------------------
// Split fp32 -> bf16 hi/lo (same layout)
// ---------------------------------------------------------------------------
__global__ void split_plain(const float* __restrict__ X,
                            __nv_bfloat16* __restrict__ H,
                            __nv_bfloat16* __restrict__ L, int n4) {
    int i = blockIdx.x * blockDim.x + threadIdx.x;
    if (i >= n4) return;
    float4 v = ((const float4*)X)[i];
    __nv_bfloat16 h0,h1,h2,h3,l0,l1,l2,l3;
    split_bf16(v.x, h0, l0); split_bf16(v.y, h1, l1);
    split_bf16(v.z, h2, l2); split_bf16(v.w, h3, l3);
    ((uint2*)H)[i] = make_uint2(pack2(h0,h1), pack2(h2,h3));
    ((uint2*)L)[i] = make_uint2(pack2(l0,l1), pack2(l2,l3));
}

// ---------------------------------------------------------------------------
// Split + transpose weights: W[k][n] (1024x1024) -> Ht[n][k], Lt[n][k]
// ---------------------------------------------------------------------------
__global__ void split_wt(const float* __restrict__ W,
                         __nv_bfloat16* __restrict__ Ht,
                         __nv_bfloat16* __restrict__ Lt) {
    __shared__ float t[32][33];
    const int n0 = blockIdx.x * 32, k0 = blockIdx.y * 32;
    const int tx = threadIdx.x, ty = threadIdx.y;
    #pragma unroll
    for (int i = 0; i < 4; i++)
        t[ty + 8 * i][tx] = W[(size_t)(k0 + ty + 8 * i) * DMODEL + n0 + tx];
    __syncthreads();
    #pragma unroll
    for (int i = 0; i < 4; i++) {
        float v = t[tx][ty + 8 * i];
        __nv_bfloat16 h, l;
        split_bf16(v, h, l);
        size_t o = (size_t)(n0 + ty + 8 * i) * DMODEL + k0 + tx;
        Ht[o] = h;
        Lt[o] = l;
    }
}

// ---------------------------------------------------------------------------
// bf16x3-split tensor-core GEMM on pre-split operands (unchanged from R5).
// ---------------------------------------------------------------------------
#define RS   44
#define TSZ  (128 * RS * 2)
#define SSTG (4 * TSZ)
#define GSMEM (2 * SSTG)

__global__ __launch_bounds__(256)
void gemm_bf16s(const __nv_bfloat16* __restrict__ AH, const __nv_bfloat16* __restrict__ AL,
                const __nv_bfloat16* __restrict__ BHt, const __nv_bfloat16* __restrict__ BLt,
                float* __restrict__ C, int M, int N, int K) {
    extern __shared__ char smem[];

    const int tid  = threadIdx.x;
    const int lane = tid & 31;
    const int wid  = tid >> 5;
    const int wm   = wid & 3;
    const int wn   = wid >> 2;
    const int g    = lane >> 2;
    const int tg   = lane & 3;
    const int row0 = blockIdx.y * 128;
    const int col0 = blockIdx.x * 128;

    const int am = tid >> 1;
    const int ak = (tid & 1) * 16;
    const int bn = tid & 127;
    const int bk = (tid >> 7) * 16;

    float acc[2][8][4];
    #pragma unroll
    for (int i = 0; i < 2; i++)
        #pragma unroll
        for (int j = 0; j < 8; j++)
            #pragma unroll
            for (int q = 0; q < 4; q++) acc[i][j][q] = 0.f;

    uint4 ph[2], pl[2], qh[2], ql[2];

    auto fetch = [&](int kc) {
        size_t ab = (size_t)(row0 + am) * K + kc + ak;
        ph[0] = *(const uint4*)&AH[ab];      ph[1] = *(const uint4*)&AH[ab + 8];
        pl[0] = *(const uint4*)&AL[ab];      pl[1] = *(const uint4*)&AL[ab + 8];
        size_t bb = (size_t)(col0 + bn) * K + kc + bk;
        qh[0] = *(const uint4*)&BHt[bb];     qh[1] = *(const uint4*)&BHt[bb + 8];
        ql[0] = *(const uint4*)&BLt[bb];     ql[1] = *(const uint4*)&BLt[bb + 8];
    };
    auto st4 = [&](__nv_bfloat16* p, int off, const uint4& a, const uint4& b) {
        *(uint2*)&p[off]      = make_uint2(a.x, a.y);
        *(uint2*)&p[off + 4]  = make_uint2(a.z, a.w);
        *(uint2*)&p[off + 8]  = make_uint2(b.x, b.y);
        *(uint2*)&p[off + 12] = make_uint2(b.z, b.w);
    };
    auto stage_store = [&](int st) {
        __nv_bfloat16* ah = (__nv_bfloat16*)(smem + st * SSTG);
        __nv_bfloat16* al = (__nv_bfloat16*)(smem + st * SSTG + TSZ);
        __nv_bfloat16* bh = (__nv_bfloat16*)(smem + st * SSTG + 2 * TSZ);
        __nv_bfloat16* bl = (__nv_bfloat16*)(smem + st * SSTG + 3 * TSZ);
        st4(ah, am * RS + ak, ph[0], ph[1]);
        st4(al, am * RS + ak, pl[0], pl[1]);
        st4(bh, bn * RS + bk, qh[0], qh[1]);
        st4(bl, bn * RS + bk, ql[0], ql[1]);
    };

    fetch(0);
    stage_store(0);
    __syncthreads();

    const int iters = K / 32;
    for (int it = 0; it < iters; it++) {
        const int cur = it & 1;
        if (it + 1 < iters) fetch((it + 1) * 32);

        const __nv_bfloat16* ah = (const __nv_bfloat16*)(smem + cur * SSTG);
        const __nv_bfloat16* al = (const __nv_bfloat16*)(smem + cur * SSTG + TSZ);
        const __nv_bfloat16* bh = (const __nv_bfloat16*)(smem + cur * SSTG + 2 * TSZ);
        const __nv_bfloat16* bl = (const __nv_bfloat16*)(smem + cur * SSTG + 3 * TSZ);

        #pragma unroll
        for (int ks = 0; ks < 32; ks += 16) {
            uint32_t fah[2][4], fal[2][4];
            #pragma unroll
            for (int mi = 0; mi < 2; mi++) {
                int mb = wm * 32 + mi * 16;
                int r0 = (mb + g) * RS + ks + 2 * tg;
                int r1 = (mb + g + 8) * RS + ks + 2 * tg;
                fah[mi][0] = *(const uint32_t*)&ah[r0];
                fah[mi][1] = *(const uint32_t*)&ah[r1];
                fah[mi][2] = *(const uint32_t*)&ah[r0 + 8];
                fah[mi][3] = *(const uint32_t*)&ah[r1 + 8];
                fal[mi][0] = *(const uint32_t*)&al[r0];
                fal[mi][1] = *(const uint32_t*)&al[r1];
                fal[mi][2] = *(const uint32_t*)&al[r0 + 8];
                fal[mi][3] = *(const uint32_t*)&al[r1 + 8];
            }
            #pragma unroll
            for (int ni = 0; ni < 8; ni++) {
                int nb = wn * 64 + ni * 8;
                int c0 = (nb + g) * RS + ks + 2 * tg;
                uint32_t fbh[2], fbl[2];
                fbh[0] = *(const uint32_t*)&bh[c0];
                fbh[1] = *(const uint32_t*)&bh[c0 + 8];
                fbl[0] = *(const uint32_t*)&bl[c0];
                fbl[1] = *(const uint32_t*)&bl[c0 + 8];
                #pragma unroll
                for (int mi = 0; mi < 2; mi++) {
                    mma_bf16(acc[mi][ni], fah[mi], fbh);
                    mma_bf16(acc[mi][ni], fah[mi], fbl);
                    mma_bf16(acc[mi][ni], fal[mi], fbh);
                }
            }
        }

        if (it + 1 < iters) stage_store(cur ^ 1);
        __syncthreads();
    }

    #pragma unroll
    for (int mi = 0; mi < 2; mi++) {
        #pragma unroll
        for (int ni = 0; ni < 8; ni++) {
            int rg = row0 + wm * 32 + mi * 16 + g;
            int cg = col0 + wn * 64 + ni * 8 + tg * 2;
            *(float2*)&C[(size_t)rg * N + cg]       = make_float2(acc[mi][ni][0], acc[mi][ni][1]);
            *(float2*)&C[(size_t)(rg + 8) * N + cg] = make_float2(acc[mi][ni][2], acc[mi][ni][3]);
        }
    }
}

// ---------------------------------------------------------------------------
// In-place NeoX RoPE on Q and K
// ---------------------------------------------------------------------------
__global__ void rope_kernel(float* __restrict__ Q, float* __restrict__ K,
                            const int* __restrict__ positions) {
    int idx = blockIdx.x * blockDim.x + threadIdx.x;
    if (idx >= MROWS * NHEADS * 32) return;
    int d = idx & 31;
    int h = (idx >> 5) & 15;
    int m = idx >> 9;
    int s = m & (SEQ - 1);

    float pos = (float)positions[s];
    float inv_freq = exp2f((float)d * -0.4152410118609203f);
    float ang = pos * inv_freq;
    float c, sn;
    sincosf(ang, &sn, &c);

    size_t base = (size_t)m * DMODEL + h * DHEAD + d;
    float q1 = Q[base], q2 = Q[base + 32];
    Q[base]      = q1 * c - q2 * sn;
    Q[base + 32] = q2 * c + q1 * sn;
    float k1 = K[base], k2 = K[base + 32];
    K[base]      = k1 * c - k2 * sn;
    K[base + 32] = k2 * c + k1 * sn;
}

// ---------------------------------------------------------------------------
// Flash attention v3: fp16 m16n8k16 MMA, register-resident softmax (FA2 style).
// BQ=128, 8 warps x m16 (full n=64 per warp). BK=64.
// Scores stay in fp32 registers; only K/V/P rounded to fp16 (== tf32 precision).
// grid: (SEQ/128, B*H) = (16, 64). 256 threads. 2 syncs per k-tile.
// ---------------------------------------------------------------------------
#define AST 66   // smem row stride (halves); 132B = 4B-aligned, low-conflict

__global__ __launch_bounds__(256, 2)
void attn3_kernel(const float* __restrict__ Q, const float* __restrict__ K,
                  const float* __restrict__ V, float* __restrict__ O) {
    __shared__ __half sh[128 * AST];   // prologue: Qs[128][AST]; loop: Kn[0..63], Vt[64..127]
    __half* Qs = sh;
    __half* Kn = sh;                   // [key][d]
    __half* Vt = sh + 64 * AST;        // [d][key]

    const int tid  = threadIdx.x;
    const int lane = tid & 31;
    const int wid  = tid >> 5;
    const int g    = lane >> 2;
    const int tg   = lane & 3;
    const int m0   = wid * 16;

    const int bh = blockIdx.y;
    const int b  = bh >> 4;
    const int h  = bh & 15;
    const int q0 = blockIdx.x * 128;
    const size_t base = (size_t)b * SEQ * DMODEL + (size_t)h * DHEAD;

    // Prologue: Q tile -> fp16 smem [q][d]
    {
        const int lr = tid >> 4;
        const int d4 = (tid & 15) * 4;
        #pragma unroll
        for (int i = 0; i < 8; i++) {
            int r = lr + i * 16;
            float4 qv = *(const float4*)&Q[base + (size_t)(q0 + r) * DMODEL + d4];
            *(uint32_t*)&Qs[r * AST + d4]     = packh2(qv.x, qv.y);
            *(uint32_t*)&Qs[r * AST + d4 + 2] = packh2(qv.z, qv.w);
        }
    }
    __syncthreads();

    // Hoist Q A-fragments: 4 k16-steps
    uint32_t qa[4][4];
    #pragma unroll
    for (int kst = 0; kst < 4; kst++) {
        int ks = kst * 16 + 2 * tg;
        qa[kst][0] = *(uint32_t*)&Qs[(m0 + g) * AST + ks];
        qa[kst][1] = *(uint32_t*)&Qs[(m0 + g + 8) * AST + ks];
        qa[kst][2] = *(uint32_t*)&Qs[(m0 + g) * AST + ks + 8];
        qa[kst][3] = *(uint32_t*)&Qs[(m0 + g + 8) * AST + ks + 8];
    }

    float accO[8][4];
    #pragma unroll
    for (int i = 0; i < 8; i++)
        #pragma unroll
        for (int j = 0; j < 4; j++) accO[i][j] = 0.f;
    float mr0 = -INFINITY, mr1 = -INFINITY, lr0 = 0.f, lr1 = 0.f;

    for (int kt = 0; kt < SEQ; kt += 64) {
        __syncthreads();   // Q-hoist / prior-tile fragment reads complete
        {
            const int lr = tid >> 4;
            const int d4 = (tid & 15) * 4;
            #pragma unroll
            for (int i = 0; i < 4; i++) {
                int r = lr + i * 16;
                float4 kv = *(const float4*)&K[base + (size_t)(kt + r) * DMODEL + d4];
                *(uint32_t*)&Kn[r * AST + d4]     = packh2(kv.x, kv.y);
                *(uint32_t*)&Kn[r * AST + d4 + 2] = packh2(kv.z, kv.w);
                float4 vv = *(const float4*)&V[base + (size_t)(kt + r) * DMODEL + d4];
                Vt[(d4 + 0) * AST + r] = __float2half_rn(vv.x);
                Vt[(d4 + 1) * AST + r] = __float2half_rn(vv.y);
                Vt[(d4 + 2) * AST + r] = __float2half_rn(vv.z);
                Vt[(d4 + 3) * AST + r] = __float2half_rn(vv.w);
            }
        }
        __syncthreads();

        // S = Q K^T : warp computes m16 x n64 in registers
        float s[8][4];
        #pragma unroll
        for (int i = 0; i < 8; i++)
            #pragma unroll
            for (int j = 0; j < 4; j++) s[i][j] = 0.f;
        #pragma unroll
        for (int kst = 0; kst < 4; kst++) {
            int ks = kst * 16 + 2 * tg;
            #pragma unroll
            for (int ni = 0; ni < 8; ni++) {
                uint32_t bb[2];
                bb[0] = *(uint32_t*)&Kn[(ni * 8 + g) * AST + ks];
                bb[1] = *(uint32_t*)&Kn[(ni * 8 + g) * AST + ks + 8];
                mma_f16(s[ni], qa[kst], bb);
            }
        }

        // Register softmax (rows m0+g and m0+g+8)
        float nm0 = mr0, nm1 = mr1;
        #pragma unroll
        for (int ni = 0; ni < 8; ni++) {
            nm0 = fmaxf(nm0, fmaxf(s[ni][0], s[ni][1]));
            nm1 = fmaxf(nm1, fmaxf(s[ni][2], s[ni][3]));
        }
        nm0 = fmaxf(nm0, __shfl_xor_sync(0xffffffffu, nm0, 1));
        nm0 = fmaxf(nm0, __shfl_xor_sync(0xffffffffu, nm0, 2));
        nm1 = fmaxf(nm1, __shfl_xor_sync(0xffffffffu, nm1, 1));
        nm1 = fmaxf(nm1, __shfl_xor_sync(0xffffffffu, nm1, 2));
        float a0 = __expf(mr0 - nm0);
        float a1 = __expf(mr1 - nm1);
        float sum0 = 0.f, sum1 = 0.f;
        #pragma unroll
        for (int ni = 0; ni < 8; ni++) {
            s[ni][0] = __expf(s[ni][0] - nm0); sum0 += s[ni][0];
            s[ni][1] = __expf(s[ni][1] - nm0); sum0 += s[ni][1];
            s[ni][2] = __expf(s[ni][2] - nm1); sum1 += s[ni][2];
            s[ni][3] = __expf(s[ni][3] - nm1); sum1 += s[ni][3];
        }
        sum0 += __shfl_xor_sync(0xffffffffu, sum0, 1);
        sum0 += __shfl_xor_sync(0xffffffffu, sum0, 2);
        sum1 += __shfl_xor_sync(0xffffffffu, sum1, 1);
        sum1 += __shfl_xor_sync(0xffffffffu, sum1, 2);
        lr0 = lr0 * a0 + sum0;
        lr1 = lr1 * a1 + sum1;
        mr0 = nm0; mr1 = nm1;

        // Rescale O accumulators
        #pragma unroll
        for (int ni = 0; ni < 8; ni++) {
            accO[ni][0] *= a0; accO[ni][1] *= a0;
            accO[ni][2] *= a1; accO[ni][3] *= a1;
        }

        // O += P V : P fragments packed straight from the S accumulator
        #pragma unroll
        for (int kst = 0; kst < 4; kst++) {
            uint32_t pf[4];
            pf[0] = packh2(s[2 * kst][0],     s[2 * kst][1]);
            pf[1] = packh2(s[2 * kst][2],     s[2 * kst][3]);
            pf[2] = packh2(s[2 * kst + 1][0], s[2 * kst + 1][1]);
            pf[3] = packh2(s[2 * kst + 1][2], s[2 * kst + 1][3]);
            int ks = kst * 16 + 2 * tg;
            #pragma unroll
            for (int ni = 0; ni < 8; ni++) {
                uint32_t bb[2];
                bb[0] = *(uint32_t*)&Vt[(ni * 8 + g) * AST + ks];
                bb[1] = *(uint32_t*)&Vt[(ni * 8 + g) * AST + ks + 8];
                mma_f16(accO[ni], pf, bb);
            }
        }
    }

    // Final normalize + store
    {
        float i0 = 1.f / lr0;
        float i1 = 1.f / lr1;
        #pragma unroll
        for (int ni = 0; ni < 8; ni++) {
            int c = ni * 8 + 2 * tg;
            *(float2*)&O[base + (size_t)(q0 + m0 + g) * DMODEL + c] =
                make_float2(accO[ni][0] * i0, accO[ni][1] * i0);
            *(float2*)&O[base + (size_t)(q0 + m0 + g + 8) * DMODEL + c] =
                make_float2(accO[ni][2] * i1, accO[ni][3] * i1);
        }
    }
}

// ---------------------------------------------------------------------------
// Launch
// ---------------------------------------------------------------------------
extern "C" void kernel_launch(void* const* d_in, const int* in_sizes, int n_in,
                              void* d_out, int out_size) {
    const int*   positions = (const int*)d_in[0];
    const float* X  = (const float*)d_in[1];
    const float* wq = (const float*)d_in[2];
    const float* wk = (const float*)d_in[3];
    const float* wv = (const float*)d_in[4];
    const float* wo = (const float*)d_in[5];
    float* out = (float*)d_out;

    float* bufs = nullptr;
    cudaGetSymbolAddress((void**)&bufs, g_bufs);
    float* Qp = bufs;
    float* Kp = bufs + NB_ELEM;
    float* Vp = bufs + 2 * NB_ELEM;
    float* Op = bufs + 3 * NB_ELEM;

    __nv_bfloat16 *xh, *xl, *oh, *ol, *wht, *wlt;
    cudaGetSymbolAddress((void**)&xh, g_xh);
    cudaGetSymbolAddress((void**)&xl, g_xl);
    cudaGetSymbolAddress((void**)&oh, g_oh);
    cudaGetSymbolAddress((void**)&ol, g_ol);
    cudaGetSymbolAddress((void**)&wht, g_wht);
    cudaGetSymbolAddress((void**)&wlt, g_wlt);
    const size_t WSZ = (size_t)DMODEL * DMODEL;

    // Pre-split inputs and weights
    int n4 = (int)(NB_ELEM / 4);
    split_plain<<<(n4 + 255) / 256, 256>>>(X, xh, xl, n4);
    dim3 wtg(DMODEL / 32, DMODEL / 32), wtb(32, 8);
    split_wt<<<wtg, wtb>>>(wq, wht + 0 * WSZ, wlt + 0 * WSZ);
    split_wt<<<wtg, wtb>>>(wk, wht + 1 * WSZ, wlt + 1 * WSZ);
    split_wt<<<wtg, wtb>>>(wv, wht + 2 * WSZ, wlt + 2 * WSZ);
    split_wt<<<wtg, wtb>>>(wo, wht + 3 * WSZ, wlt + 3 * WSZ);

    cudaFuncSetAttribute(gemm_bf16s, cudaFuncAttributeMaxDynamicSharedMemorySize, GSMEM);
    dim3 ggrid(DMODEL / 128, MROWS / 128);   // (8, 64)
    gemm_bf16s<<<ggrid, 256, GSMEM>>>(xh, xl, wht + 0 * WSZ, wlt + 0 * WSZ, Qp, MROWS, DMODEL, DMODEL);
    gemm_bf16s<<<ggrid, 256, GSMEM>>>(xh, xl, wht + 1 * WSZ, wlt + 1 * WSZ, Kp, MROWS, DMODEL, DMODEL);
    gemm_bf16s<<<ggrid, 256, GSMEM>>>(xh, xl, wht + 2 * WSZ, wlt + 2 * WSZ, Vp, MROWS, DMODEL, DMODEL);

    int pairs = MROWS * NHEADS * 32;
    rope_kernel<<<(pairs + 255) / 256, 256>>>(Qp, Kp, positions);

    attn3_kernel<<<dim3(SEQ / 128, BATCH * NHEADS), 256>>>(Qp, Kp, Vp, Op);

    split_plain<<<(n4 + 255) / 256, 256>>>(Op, oh, ol, n4);
    gemm_bf16s<<<ggrid, 256, GSMEM>>>(oh, ol, wht + 3 * WSZ, wlt + 3 * WSZ, out, MROWS, DMODEL, DMODEL);
}

// round 7
// speedup vs baseline: 2.4796x; 1.0426x over previous
#include <cuda_runtime.h>
#include <cuda_bf16.h>
#include <cuda_fp16.h>
#include <math.h>
#include <stdint.h>

// Problem constants
#define BATCH   4
#define SEQ     2048
#define DMODEL  1024
#define NHEADS  16
#define DHEAD   64
#define MROWS   (BATCH * SEQ)            // 8192
#define NB_ELEM ((size_t)MROWS * DMODEL)

// fp32 scratch: Q, K, V projections + attention output
__device__ float g_bufs[4][MROWS * DMODEL];
// bf16 hi/lo pre-split buffers
__device__ __nv_bfloat16 g_xh[MROWS * DMODEL];
__device__ __nv_bfloat16 g_xl[MROWS * DMODEL];
__device__ __nv_bfloat16 g_oh[MROWS * DMODEL];
__device__ __nv_bfloat16 g_ol[MROWS * DMODEL];
__device__ __nv_bfloat16 g_wht[4][DMODEL * DMODEL];  // transposed [n][k]
__device__ __nv_bfloat16 g_wlt[4][DMODEL * DMODEL];

// ---------------------------------------------------------------------------
// Helpers
// ---------------------------------------------------------------------------
__device__ __forceinline__ uint32_t smem_u32(const void* p) {
    uint32_t a;
    asm("{ .reg .u64 t; cvta.to.shared.u64 t, %1; cvt.u32.u64 %0, t; }" : "=r"(a) : "l"(p));
    return a;
}
__device__ __forceinline__ void split_bf16(float x, __nv_bfloat16& h, __nv_bfloat16& l) {
    h = __float2bfloat16_rn(x);
    l = __float2bfloat16_rn(x - __bfloat162float(h));
}
__device__ __forceinline__ uint32_t pack2(__nv_bfloat16 a, __nv_bfloat16 b) {
    __nv_bfloat162 t = __halves2bfloat162(a, b);
    return *reinterpret_cast<uint32_t*>(&t);
}
__device__ __forceinline__ uint32_t packh2(float a, float b) {
    __half2 t = __floats2half2_rn(a, b);
    return *reinterpret_cast<uint32_t*>(&t);
}
__device__ __forceinline__ void mma_bf16(float* c, const uint32_t* a, const uint32_t* b) {
    asm volatile(
        "mma.sync.aligned.m16n8k16.row.col.f32.bf16.bf16.f32 "
        "{%0,%1,%2,%3}, {%4,%5,%6,%7}, {%8,%9}, {%0,%1,%2,%3};"
        : "+f"(c[0]), "+f"(c[1]), "+f"(c[2]), "+f"(c[3])
        : "r"(a[0]), "r"(a[1]), "r"(a[2]), "r"(a[3]), "r"(b[0]), "r"(b[1]));
}
__device__ __forceinline__ void mma_f16(float* c, const uint32_t* a, const uint32_t* b) {
    asm volatile(
        "mma.sync.aligned.m16n8k16.row.col.f32.f16.f16.f32 "
        "{%0,%1,%2,%3}, {%4,%5,%6,%7}, {%8,%9}, {%0,%1,%2,%3};"
        : "+f"(c[0]), "+f"(c[1]), "+f"(c[2]), "+f"(c[3])
        : "r"(a[0]), "r"(a[1]), "r"(a[2]), "r"(a[3]), "r"(b[0]), "r"(b[1]));
}
__device__ __forceinline__ void ldsm4(uint32_t* r, uint32_t addr) {
    asm volatile("ldmatrix.sync.aligned.m8n8.x4.shared.b16 {%0,%1,%2,%3}, [%4];"
                 : "=r"(r[0]), "=r"(r[1]), "=r"(r[2]), "=r"(r[3]) : "r"(addr));
}

// ---------------------------------------------------------------------------
// Split fp32 -> bf16 hi/lo (same layout)
// ---------------------------------------------------------------------------
__global__ void split_plain(const float* __restrict__ X,
                            __nv_bfloat16* __restrict__ H,
                            __nv_bfloat16* __restrict__ L, int n4) {
    int i = blockIdx.x * blockDim.x + threadIdx.x;
    if (i >= n4) return;
    float4 v = ((const float4*)X)[i];
    __nv_bfloat16 h0,h1,h2,h3,l0,l1,l2,l3;
    split_bf16(v.x, h0, l0); split_bf16(v.y, h1, l1);
    split_bf16(v.z, h2, l2); split_bf16(v.w, h3, l3);
    ((uint2*)H)[i] = make_uint2(pack2(h0,h1), pack2(h2,h3));
    ((uint2*)L)[i] = make_uint2(pack2(l0,l1), pack2(l2,l3));
}

// ---------------------------------------------------------------------------
// Split + transpose weights: W[k][n] (1024x1024) -> Ht[n][k], Lt[n][k]
// ---------------------------------------------------------------------------
__global__ void split_wt(const float* __restrict__ W,
                         __nv_bfloat16* __restrict__ Ht,
                         __nv_bfloat16* __restrict__ Lt) {
    __shared__ float t[32][33];
    const int n0 = blockIdx.x * 32, k0 = blockIdx.y * 32;
    const int tx = threadIdx.x, ty = threadIdx.y;
    #pragma unroll
    for (int i = 0; i < 4; i++)
        t[ty + 8 * i][tx] = W[(size_t)(k0 + ty + 8 * i) * DMODEL + n0 + tx];
    __syncthreads();
    #pragma unroll
    for (int i = 0; i < 4; i++) {
        float v = t[tx][ty + 8 * i];
        __nv_bfloat16 h, l;
        split_bf16(v, h, l);
        size_t o = (size_t)(n0 + ty + 8 * i) * DMODEL + k0 + tx;
        Ht[o] = h;
        Lt[o] = l;
    }
}

// ---------------------------------------------------------------------------
// bf16x3-split tensor-core GEMM with ldmatrix fragment loads.
// C[M,N] = A[M,K]*B[K,N]; A as AH/AL [m][k]; B as BHt/BLt [n][k].
// CTA 128x128, BK=32, 256 threads (8 warps: 4m x 2n, warp tile 32x64).
// smem row stride 48 halves (96B, 16B-aligned for LDSM).
// ---------------------------------------------------------------------------
#define RS   48
#define TSZ  (128 * RS * 2)          // 12288 bytes
#define SSTG (4 * TSZ)               // 49152
#define GSMEM (2 * SSTG)             // 98304

__global__ __launch_bounds__(256)
void gemm_bf16s(const __nv_bfloat16* __restrict__ AH, const __nv_bfloat16* __restrict__ AL,
                const __nv_bfloat16* __restrict__ BHt, const __nv_bfloat16* __restrict__ BLt,
                float* __restrict__ C, int M, int N, int K) {
    extern __shared__ char smem[];
    const uint32_t sb = smem_u32(smem);

    const int tid  = threadIdx.x;
    const int lane = tid & 31;
    const int wid  = tid >> 5;
    const int wm   = wid & 3;
    const int wn   = wid >> 2;
    const int g    = lane >> 2;
    const int tg   = lane & 3;
    const int row0 = blockIdx.y * 128;
    const int col0 = blockIdx.x * 128;

    const int am = tid >> 1;
    const int ak = (tid & 1) * 16;
    const int bn = tid & 127;
    const int bk = (tid >> 7) * 16;

    // ldmatrix per-lane source rows
    const int arow  = wm * 32 + (lane & 15);          // + mi*16
    const int akoff = (lane >> 4) * 8;                // k half
    const int brow  = wn * 64 + (lane & 7) + ((lane >> 4) << 3);  // + p*16
    const int bkoff = ((lane >> 3) & 1) * 8;

    float acc[2][8][4];
    #pragma unroll
    for (int i = 0; i < 2; i++)
        #pragma unroll
        for (int j = 0; j < 8; j++)
            #pragma unroll
            for (int q = 0; q < 4; q++) acc[i][j][q] = 0.f;

    uint4 ph[2], pl[2], qh[2], ql[2];

    auto fetch = [&](int kc) {
        size_t ab = (size_t)(row0 + am) * K + kc + ak;
        ph[0] = *(const uint4*)&AH[ab];      ph[1] = *(const uint4*)&AH[ab + 8];
        pl[0] = *(const uint4*)&AL[ab];      pl[1] = *(const uint4*)&AL[ab + 8];
        size_t bb = (size_t)(col0 + bn) * K + kc + bk;
        qh[0] = *(const uint4*)&BHt[bb];     qh[1] = *(const uint4*)&BHt[bb + 8];
        ql[0] = *(const uint4*)&BLt[bb];     ql[1] = *(const uint4*)&BLt[bb + 8];
    };
    auto st4 = [&](__nv_bfloat16* p, int off, const uint4& a, const uint4& b) {
        *(uint2*)&p[off]      = make_uint2(a.x, a.y);
        *(uint2*)&p[off + 4]  = make_uint2(a.z, a.w);
        *(uint2*)&p[off + 8]  = make_uint2(b.x, b.y);
        *(uint2*)&p[off + 12] = make_uint2(b.z, b.w);
    };
    auto stage_store = [&](int st) {
        __nv_bfloat16* ah = (__nv_bfloat16*)(smem + st * SSTG);
        __nv_bfloat16* al = (__nv_bfloat16*)(smem + st * SSTG + TSZ);
        __nv_bfloat16* bh = (__nv_bfloat16*)(smem + st * SSTG + 2 * TSZ);
        __nv_bfloat16* bl = (__nv_bfloat16*)(smem + st * SSTG + 3 * TSZ);
        st4(ah, am * RS + ak, ph[0], ph[1]);
        st4(al, am * RS + ak, pl[0], pl[1]);
        st4(bh, bn * RS + bk, qh[0], qh[1]);
        st4(bl, bn * RS + bk, ql[0], ql[1]);
    };

    fetch(0);
    stage_store(0);
    __syncthreads();

    const int iters = K / 32;
    for (int it = 0; it < iters; it++) {
        const int cur = it & 1;
        if (it + 1 < iters) fetch((it + 1) * 32);

        const uint32_t ahb = sb + cur * SSTG;
        const uint32_t alb = ahb + TSZ;
        const uint32_t bhb = ahb + 2 * TSZ;
        const uint32_t blb = ahb + 3 * TSZ;

        #pragma unroll
        for (int ks = 0; ks < 32; ks += 16) {
            uint32_t fah[2][4], fal[2][4];
            #pragma unroll
            for (int mi = 0; mi < 2; mi++) {
                uint32_t off = (uint32_t)(((arow + mi * 16) * RS + ks + akoff) * 2);
                ldsm4(fah[mi], ahb + off);
                ldsm4(fal[mi], alb + off);
            }
            #pragma unroll
            for (int p = 0; p < 4; p++) {
                uint32_t off = (uint32_t)(((brow + p * 16) * RS + ks + bkoff) * 2);
                uint32_t fbh[4], fbl[4];
                ldsm4(fbh, bhb + off);
                ldsm4(fbl, blb + off);
                #pragma unroll
                for (int mi = 0; mi < 2; mi++) {
                    mma_bf16(acc[mi][2 * p],     fah[mi], fbh);
                    mma_bf16(acc[mi][2 * p],     fah[mi], fbl);
                    mma_bf16(acc[mi][2 * p],     fal[mi], fbh);
                    mma_bf16(acc[mi][2 * p + 1], fah[mi], fbh + 2);
                    mma_bf16(acc[mi][2 * p + 1], fah[mi], fbl + 2);
                    mma_bf16(acc[mi][2 * p + 1], fal[mi], fbh + 2);
                }
            }
        }

        if (it + 1 < iters) stage_store(cur ^ 1);
        __syncthreads();
    }

    #pragma unroll
    for (int mi = 0; mi < 2; mi++) {
        #pragma unroll
        for (int ni = 0; ni < 8; ni++) {
            int rg = row0 + wm * 32 + mi * 16 + g;
            int cg = col0 + wn * 64 + ni * 8 + tg * 2;
            *(float2*)&C[(size_t)rg * N + cg]       = make_float2(acc[mi][ni][0], acc[mi][ni][1]);
            *(float2*)&C[(size_t)(rg + 8) * N + cg] = make_float2(acc[mi][ni][2], acc[mi][ni][3]);
        }
    }
}

// ---------------------------------------------------------------------------
// In-place NeoX RoPE on Q and K
// ---------------------------------------------------------------------------
__global__ void rope_kernel(float* __restrict__ Q, float* __restrict__ K,
                            const int* __restrict__ positions) {
    int idx = blockIdx.x * blockDim.x + threadIdx.x;
    if (idx >= MROWS * NHEADS * 32) return;
    int d = idx & 31;
    int h = (idx >> 5) & 15;
    int m = idx >> 9;
    int s = m & (SEQ - 1);

    float pos = (float)positions[s];
    float inv_freq = exp2f((float)d * -0.4152410118609203f);
    float ang = pos * inv_freq;
    float c, sn;
    sincosf(ang, &sn, &c);

    size_t base = (size_t)m * DMODEL + h * DHEAD + d;
    float q1 = Q[base], q2 = Q[base + 32];
    Q[base]      = q1 * c - q2 * sn;
    Q[base + 32] = q2 * c + q1 * sn;
    float k1 = K[base], k2 = K[base + 32];
    K[base]      = k1 * c - k2 * sn;
    K[base + 32] = k2 * c + k1 * sn;
}

// ---------------------------------------------------------------------------
// Flash attention v3: fp16 m16n8k16 MMA, register-resident softmax (FA2).
// BQ=128, 8 warps x m16 (full n=64 per warp). BK=64. (unchanged from R6)
// ---------------------------------------------------------------------------
#define AST 66

__global__ __launch_bounds__(256, 2)
void attn3_kernel(const float* __restrict__ Q, const float* __restrict__ K,
                  const float* __restrict__ V, float* __restrict__ O) {
    __shared__ __half sh[128 * AST];
    __half* Qs = sh;
    __half* Kn = sh;                   // [key][d]
    __half* Vt = sh + 64 * AST;        // [d][key]

    const int tid  = threadIdx.x;
    const int lane = tid & 31;
    const int wid  = tid >> 5;
    const int g    = lane >> 2;
    const int tg   = lane & 3;
    const int m0   = wid * 16;

    const int bh = blockIdx.y;
    const int b  = bh >> 4;
    const int h  = bh & 15;
    const int q0 = blockIdx.x * 128;
    const size_t base = (size_t)b * SEQ * DMODEL + (size_t)h * DHEAD;

    {
        const int lr = tid >> 4;
        const int d4 = (tid & 15) * 4;
        #pragma unroll
        for (int i = 0; i < 8; i++) {
            int r = lr + i * 16;
            float4 qv = *(const float4*)&Q[base + (size_t)(q0 + r) * DMODEL + d4];
            *(uint32_t*)&Qs[r * AST + d4]     = packh2(qv.x, qv.y);
            *(uint32_t*)&Qs[r * AST + d4 + 2] = packh2(qv.z, qv.w);
        }
    }
    __syncthreads();

    uint32_t qa[4][4];
    #pragma unroll
    for (int kst = 0; kst < 4; kst++) {
        int ks = kst * 16 + 2 * tg;
        qa[kst][0] = *(uint32_t*)&Qs[(m0 + g) * AST + ks];
        qa[kst][1] = *(uint32_t*)&Qs[(m0 + g + 8) * AST + ks];
        qa[kst][2] = *(uint32_t*)&Qs[(m0 + g) * AST + ks + 8];
        qa[kst][3] = *(uint32_t*)&Qs[(m0 + g + 8) * AST + ks + 8];
    }

    float accO[8][4];
    #pragma unroll
    for (int i = 0; i < 8; i++)
        #pragma unroll
        for (int j = 0; j < 4; j++) accO[i][j] = 0.f;
    float mr0 = -INFINITY, mr1 = -INFINITY, lr0 = 0.f, lr1 = 0.f;

    for (int kt = 0; kt < SEQ; kt += 64) {
        __syncthreads();
        {
            const int lr = tid >> 4;
            const int d4 = (tid & 15) * 4;
            #pragma unroll
            for (int i = 0; i < 4; i++) {
                int r = lr + i * 16;
                float4 kv = *(const float4*)&K[base + (size_t)(kt + r) * DMODEL + d4];
                *(uint32_t*)&Kn[r * AST + d4]     = packh2(kv.x, kv.y);
                *(uint32_t*)&Kn[r * AST + d4 + 2] = packh2(kv.z, kv.w);
                float4 vv = *(const float4*)&V[base + (size_t)(kt + r) * DMODEL + d4];
                Vt[(d4 + 0) * AST + r] = __float2half_rn(vv.x);
                Vt[(d4 + 1) * AST + r] = __float2half_rn(vv.y);
                Vt[(d4 + 2) * AST + r] = __float2half_rn(vv.z);
                Vt[(d4 + 3) * AST + r] = __float2half_rn(vv.w);
            }
        }
        __syncthreads();

        float s[8][4];
        #pragma unroll
        for (int i = 0; i < 8; i++)
            #pragma unroll
            for (int j = 0; j < 4; j++) s[i][j] = 0.f;
        #pragma unroll
        for (int kst = 0; kst < 4; kst++) {
            int ks = kst * 16 + 2 * tg;
            #pragma unroll
            for (int ni = 0; ni < 8; ni++) {
                uint32_t bb[2];
                bb[0] = *(uint32_t*)&Kn[(ni * 8 + g) * AST + ks];
                bb[1] = *(uint32_t*)&Kn[(ni * 8 + g) * AST + ks + 8];
                mma_f16(s[ni], qa[kst], bb);
            }
        }

        float nm0 = mr0, nm1 = mr1;
        #pragma unroll
        for (int ni = 0; ni < 8; ni++) {
            nm0 = fmaxf(nm0, fmaxf(s[ni][0], s[ni][1]));
            nm1 = fmaxf(nm1, fmaxf(s[ni][2], s[ni][3]));
        }
        nm0 = fmaxf(nm0, __shfl_xor_sync(0xffffffffu, nm0, 1));
        nm0 = fmaxf(nm0, __shfl_xor_sync(0xffffffffu, nm0, 2));
        nm1 = fmaxf(nm1, __shfl_xor_sync(0xffffffffu, nm1, 1));
        nm1 = fmaxf(nm1, __shfl_xor_sync(0xffffffffu, nm1, 2));
        float a0 = __expf(mr0 - nm0);
        float a1 = __expf(mr1 - nm1);
        float sum0 = 0.f, sum1 = 0.f;
        #pragma unroll
        for (int ni = 0; ni < 8; ni++) {
            s[ni][0] = __expf(s[ni][0] - nm0); sum0 += s[ni][0];
            s[ni][1] = __expf(s[ni][1] - nm0); sum0 += s[ni][1];
            s[ni][2] = __expf(s[ni][2] - nm1); sum1 += s[ni][2];
            s[ni][3] = __expf(s[ni][3] - nm1); sum1 += s[ni][3];
        }
        sum0 += __shfl_xor_sync(0xffffffffu, sum0, 1);
        sum0 += __shfl_xor_sync(0xffffffffu, sum0, 2);
        sum1 += __shfl_xor_sync(0xffffffffu, sum1, 1);
        sum1 += __shfl_xor_sync(0xffffffffu, sum1, 2);
        lr0 = lr0 * a0 + sum0;
        lr1 = lr1 * a1 + sum1;
        mr0 = nm0; mr1 = nm1;

        #pragma unroll
        for (int ni = 0; ni < 8; ni++) {
            accO[ni][0] *= a0; accO[ni][1] *= a0;
            accO[ni][2] *= a1; accO[ni][3] *= a1;
        }

        #pragma unroll
        for (int kst = 0; kst < 4; kst++) {
            uint32_t pf[4];
            pf[0] = packh2(s[2 * kst][0],     s[2 * kst][1]);
            pf[1] = packh2(s[2 * kst][2],     s[2 * kst][3]);
            pf[2] = packh2(s[2 * kst + 1][0], s[2 * kst + 1][1]);
            pf[3] = packh2(s[2 * kst + 1][2], s[2 * kst + 1][3]);
            int ks = kst * 16 + 2 * tg;
            #pragma unroll
            for (int ni = 0; ni < 8; ni++) {
                uint32_t bb[2];
                bb[0] = *(uint32_t*)&Vt[(ni * 8 + g) * AST + ks];
                bb[1] = *(uint32_t*)&Vt[(ni * 8 + g) * AST + ks + 8];
                mma_f16(accO[ni], pf, bb);
            }
        }
    }

    {
        float i0 = 1.f / lr0;
        float i1 = 1.f / lr1;
        #pragma unroll
        for (int ni = 0; ni < 8; ni++) {
            int c = ni * 8 + 2 * tg;
            *(float2*)&O[base + (size_t)(q0 + m0 + g) * DMODEL + c] =
                make_float2(accO[ni][0] * i0, accO[ni][1] * i0);
            *(float2*)&O[base + (size_t)(q0 + m0 + g + 8) * DMODEL + c] =
                make_float2(accO[ni][2] * i1, accO[ni][3] * i1);
        }
    }
}

// ---------------------------------------------------------------------------
// Launch
// ---------------------------------------------------------------------------
extern "C" void kernel_launch(void* const* d_in, const int* in_sizes, int n_in,
                              void* d_out, int out_size) {
    const int*   positions = (const int*)d_in[0];
    const float* X  = (const float*)d_in[1];
    const float* wq = (const float*)d_in[2];
    const float* wk = (const float*)d_in[3];
    const float* wv = (const float*)d_in[4];
    const float* wo = (const float*)d_in[5];
    float* out = (float*)d_out;

    float* bufs = nullptr;
    cudaGetSymbolAddress((void**)&bufs, g_bufs);
    float* Qp = bufs;
    float* Kp = bufs + NB_ELEM;
    float* Vp = bufs + 2 * NB_ELEM;
    float* Op = bufs + 3 * NB_ELEM;

    __nv_bfloat16 *xh, *xl, *oh, *ol, *wht, *wlt;
    cudaGetSymbolAddress((void**)&xh, g_xh);
    cudaGetSymbolAddress((void**)&xl, g_xl);
    cudaGetSymbolAddress((void**)&oh, g_oh);
    cudaGetSymbolAddress((void**)&ol, g_ol);
    cudaGetSymbolAddress((void**)&wht, g_wht);
    cudaGetSymbolAddress((void**)&wlt, g_wlt);
    const size_t WSZ = (size_t)DMODEL * DMODEL;

    int n4 = (int)(NB_ELEM / 4);
    split_plain<<<(n4 + 255) / 256, 256>>>(X, xh, xl, n4);
    dim3 wtg(DMODEL / 32, DMODEL / 32), wtb(32, 8);
    split_wt<<<wtg, wtb>>>(wq, wht + 0 * WSZ, wlt + 0 * WSZ);
    split_wt<<<wtg, wtb>>>(wk, wht + 1 * WSZ, wlt + 1 * WSZ);
    split_wt<<<wtg, wtb>>>(wv, wht + 2 * WSZ, wlt + 2 * WSZ);
    split_wt<<<wtg, wtb>>>(wo, wht + 3 * WSZ, wlt + 3 * WSZ);

    cudaFuncSetAttribute(gemm_bf16s, cudaFuncAttributeMaxDynamicSharedMemorySize, GSMEM);
    dim3 ggrid(DMODEL / 128, MROWS / 128);   // (8, 64)
    gemm_bf16s<<<ggrid, 256, GSMEM>>>(xh, xl, wht + 0 * WSZ, wlt + 0 * WSZ, Qp, MROWS, DMODEL, DMODEL);
    gemm_bf16s<<<ggrid, 256, GSMEM>>>(xh, xl, wht + 1 * WSZ, wlt + 1 * WSZ, Kp, MROWS, DMODEL, DMODEL);
    gemm_bf16s<<<ggrid, 256, GSMEM>>>(xh, xl, wht + 2 * WSZ, wlt + 2 * WSZ, Vp, MROWS, DMODEL, DMODEL);

    int pairs = MROWS * NHEADS * 32;
    rope_kernel<<<(pairs + 255) / 256, 256>>>(Qp, Kp, positions);

    attn3_kernel<<<dim3(SEQ / 128, BATCH * NHEADS), 256>>>(Qp, Kp, Vp, Op);

    split_plain<<<(n4 + 255) / 256, 256>>>(Op, oh, ol, n4);
    gemm_bf16s<<<ggrid, 256, GSMEM>>>(oh, ol, wht + 3 * WSZ, wlt + 3 * WSZ, out, MROWS, DMODEL, DMODEL);
}

// round 8
// speedup vs baseline: 2.4886x; 1.0036x over previous
#include <cuda_runtime.h>
#include <cuda_bf16.h>
#include <cuda_fp16.h>
#include <math.h>
#include <stdint.h>

// Problem constants
#define BATCH   4
#define SEQ     2048
#define DMODEL  1024
#define NHEADS  16
#define DHEAD   64
#define MROWS   (BATCH * SEQ)            // 8192
#define NB_ELEM ((size_t)MROWS * DMODEL)

// fp32 scratch: Q, K, V projections + attention output (contiguous!)
__device__ float g_bufs[4][MROWS * DMODEL];
// bf16 hi/lo pre-split buffers
__device__ __nv_bfloat16 g_xh[MROWS * DMODEL];
__device__ __nv_bfloat16 g_xl[MROWS * DMODEL];
__device__ __nv_bfloat16 g_oh[MROWS * DMODEL];
__device__ __nv_bfloat16 g_ol[MROWS * DMODEL];
__device__ __nv_bfloat16 g_wht[4][DMODEL * DMODEL];  // transposed [n][k], contiguous
__device__ __nv_bfloat16 g_wlt[4][DMODEL * DMODEL];

// ---------------------------------------------------------------------------
// Helpers
// ---------------------------------------------------------------------------
__device__ __forceinline__ uint32_t smem_u32(const void* p) {
    uint32_t a;
    asm("{ .reg .u64 t; cvta.to.shared.u64 t, %1; cvt.u32.u64 %0, t; }" : "=r"(a) : "l"(p));
    return a;
}
__device__ __forceinline__ void split_bf16(float x, __nv_bfloat16& h, __nv_bfloat16& l) {
    h = __float2bfloat16_rn(x);
    l = __float2bfloat16_rn(x - __bfloat162float(h));
}
__device__ __forceinline__ uint32_t pack2(__nv_bfloat16 a, __nv_bfloat16 b) {
    __nv_bfloat162 t = __halves2bfloat162(a, b);
    return *reinterpret_cast<uint32_t*>(&t);
}
__device__ __forceinline__ uint32_t packh2(float a, float b) {
    __half2 t = __floats2half2_rn(a, b);
    return *reinterpret_cast<uint32_t*>(&t);
}
// NOTE: non-volatile — pure register ops; lets ptxas schedule around latency.
__device__ __forceinline__ void mma_bf16(float* c, const uint32_t* a, const uint32_t* b) {
    asm("mma.sync.aligned.m16n8k16.row.col.f32.bf16.bf16.f32 "
        "{%0,%1,%2,%3}, {%4,%5,%6,%7}, {%8,%9}, {%0,%1,%2,%3};"
        : "+f"(c[0]), "+f"(c[1]), "+f"(c[2]), "+f"(c[3])
        : "r"(a[0]), "r"(a[1]), "r"(a[2]), "r"(a[3]), "r"(b[0]), "r"(b[1]));
}
__device__ __forceinline__ void mma_f16(float* c, const uint32_t* a, const uint32_t* b) {
    asm("mma.sync.aligned.m16n8k16.row.col.f32.f16.f16.f32 "
        "{%0,%1,%2,%3}, {%4,%5,%6,%7}, {%8,%9}, {%0,%1,%2,%3};"
        : "+f"(c[0]), "+f"(c[1]), "+f"(c[2]), "+f"(c[3])
        : "r"(a[0]), "r"(a[1]), "r"(a[2]), "r"(a[3]), "r"(b[0]), "r"(b[1]));
}
__device__ __forceinline__ void ldsm4(uint32_t* r, uint32_t addr) {
    asm volatile("ldmatrix.sync.aligned.m8n8.x4.shared.b16 {%0,%1,%2,%3}, [%4];"
                 : "=r"(r[0]), "=r"(r[1]), "=r"(r[2]), "=r"(r[3]) : "r"(addr));
}

// ---------------------------------------------------------------------------
// Split fp32 -> bf16 hi/lo (same layout)
// ---------------------------------------------------------------------------
__global__ void split_plain(const float* __restrict__ X,
                            __nv_bfloat16* __restrict__ H,
                            __nv_bfloat16* __restrict__ L, int n4) {
    int i = blockIdx.x * blockDim.x + threadIdx.x;
    if (i >= n4) return;
    float4 v = ((const float4*)X)[i];
    __nv_bfloat16 h0,h1,h2,h3,l0,l1,l2,l3;
    split_bf16(v.x, h0, l0); split_bf16(v.y, h1, l1);
    split_bf16(v.z, h2, l2); split_bf16(v.w, h3, l3);
    ((uint2*)H)[i] = make_uint2(pack2(h0,h1), pack2(h2,h3));
    ((uint2*)L)[i] = make_uint2(pack2(l0,l1), pack2(l2,l3));
}

// ---------------------------------------------------------------------------
// Split + transpose weights: W[k][n] (1024x1024) -> Ht[n][k], Lt[n][k]
// ---------------------------------------------------------------------------
__global__ void split_wt(const float* __restrict__ W,
                         __nv_bfloat16* __restrict__ Ht,
                         __nv_bfloat16* __restrict__ Lt) {
    __shared__ float t[32][33];
    const int n0 = blockIdx.x * 32, k0 = blockIdx.y * 32;
    const int tx = threadIdx.x, ty = threadIdx.y;
    #pragma unroll
    for (int i = 0; i < 4; i++)
        t[ty + 8 * i][tx] = W[(size_t)(k0 + ty + 8 * i) * DMODEL + n0 + tx];
    __syncthreads();
    #pragma unroll
    for (int i = 0; i < 4; i++) {
        float v = t[tx][ty + 8 * i];
        __nv_bfloat16 h, l;
        split_bf16(v, h, l);
        size_t o = (size_t)(n0 + ty + 8 * i) * DMODEL + k0 + tx;
        Ht[o] = h;
        Lt[o] = l;
    }
}

// ---------------------------------------------------------------------------
// bf16x3-split tensor-core GEMM, pass-major MMA ordering (16-deep acc reuse
// distance). C[M,N] = A[M,K]*B[K,N]; A as AH/AL [m][k]; B as BHt/BLt [n][k].
// CTA 128x128, BK=32, 256 threads (8 warps: 4m x 2n, warp tile 32x64).
// split3 != 0: N=3072 fused QKV; output column n maps to buffer n>>10 of C
// (3 contiguous [MROWS x 1024] buffers).
// ---------------------------------------------------------------------------
#define RS   48
#define TSZ  (128 * RS * 2)          // 12288 bytes
#define SSTG (4 * TSZ)               // 49152
#define GSMEM (2 * SSTG)             // 98304

__global__ __launch_bounds__(256)
void gemm_bf16s(const __nv_bfloat16* __restrict__ AH, const __nv_bfloat16* __restrict__ AL,
                const __nv_bfloat16* __restrict__ BHt, const __nv_bfloat16* __restrict__ BLt,
                float* __restrict__ C, int M, int N, int K, int split3) {
    extern __shared__ char smem[];
    const uint32_t sb = smem_u32(smem);

    const int tid  = threadIdx.x;
    const int lane = tid & 31;
    const int wid  = tid >> 5;
    const int wm   = wid & 3;
    const int wn   = wid >> 2;
    const int g    = lane >> 2;
    const int tg   = lane & 3;
    const int row0 = blockIdx.y * 128;
    const int col0 = blockIdx.x * 128;

    const int am = tid >> 1;
    const int ak = (tid & 1) * 16;
    const int bn = tid & 127;
    const int bk = (tid >> 7) * 16;

    const int arow  = wm * 32 + (lane & 15);
    const int akoff = (lane >> 4) * 8;
    const int brow  = wn * 64 + (lane & 7) + ((lane >> 4) << 3);
    const int bkoff = ((lane >> 3) & 1) * 8;

    float acc[2][8][4];
    #pragma unroll
    for (int i = 0; i < 2; i++)
        #pragma unroll
        for (int j = 0; j < 8; j++)
            #pragma unroll
            for (int q = 0; q < 4; q++) acc[i][j][q] = 0.f;

    uint4 ph[2], pl[2], qh[2], ql[2];

    auto fetch = [&](int kc) {
        size_t ab = (size_t)(row0 + am) * K + kc + ak;
        ph[0] = *(const uint4*)&AH[ab];      ph[1] = *(const uint4*)&AH[ab + 8];
        pl[0] = *(const uint4*)&AL[ab];      pl[1] = *(const uint4*)&AL[ab + 8];
        size_t bb = (size_t)(col0 + bn) * K + kc + bk;
        qh[0] = *(const uint4*)&BHt[bb];     qh[1] = *(const uint4*)&BHt[bb + 8];
        ql[0] = *(const uint4*)&BLt[bb];     ql[1] = *(const uint4*)&BLt[bb + 8];
    };
    auto st4 = [&](__nv_bfloat16* p, int off, const uint4& a, const uint4& b) {
        *(uint2*)&p[off]      = make_uint2(a.x, a.y);
        *(uint2*)&p[off + 4]  = make_uint2(a.z, a.w);
        *(uint2*)&p[off + 8]  = make_uint2(b.x, b.y);
        *(uint2*)&p[off + 12] = make_uint2(b.z, b.w);
    };
    auto stage_store = [&](int st) {
        __nv_bfloat16* ah = (__nv_bfloat16*)(smem + st * SSTG);
        __nv_bfloat16* al = (__nv_bfloat16*)(smem + st * SSTG + TSZ);
        __nv_bfloat16* bh = (__nv_bfloat16*)(smem + st * SSTG + 2 * TSZ);
        __nv_bfloat16* bl = (__nv_bfloat16*)(smem + st * SSTG + 3 * TSZ);
        st4(ah, am * RS + ak, ph[0], ph[1]);
        st4(al, am * RS + ak, pl[0], pl[1]);
        st4(bh, bn * RS + bk, qh[0], qh[1]);
        st4(bl, bn * RS + bk, ql[0], ql[1]);
    };

    fetch(0);
    stage_store(0);
    __syncthreads();

    const int iters = K / 32;
    for (int it = 0; it < iters; it++) {
        const int cur = it & 1;
        if (it + 1 < iters) fetch((it + 1) * 32);

        const uint32_t ahb = sb + cur * SSTG;
        const uint32_t alb = ahb + TSZ;
        const uint32_t bhb = ahb + 2 * TSZ;
        const uint32_t blb = ahb + 3 * TSZ;

        #pragma unroll
        for (int ks = 0; ks < 32; ks += 16) {
            uint32_t fah[2][4], fal[2][4], fbh[4][4], fbl[4][4];
            #pragma unroll
            for (int mi = 0; mi < 2; mi++) {
                uint32_t off = (uint32_t)(((arow + mi * 16) * RS + ks + akoff) * 2);
                ldsm4(fah[mi], ahb + off);
                ldsm4(fal[mi], alb + off);
            }
            #pragma unroll
            for (int p = 0; p < 4; p++) {
                uint32_t off = (uint32_t)(((brow + p * 16) * RS + ks + bkoff) * 2);
                ldsm4(fbh[p], bhb + off);
                ldsm4(fbl[p], blb + off);
            }
            // Pass 1: hi*hi — 16 distinct accumulator quads
            #pragma unroll
            for (int p = 0; p < 4; p++)
                #pragma unroll
                for (int mi = 0; mi < 2; mi++) {
                    mma_bf16(acc[mi][2 * p],     fah[mi], fbh[p]);
                    mma_bf16(acc[mi][2 * p + 1], fah[mi], fbh[p] + 2);
                }
            // Pass 2: hi*lo
            #pragma unroll
            for (int p = 0; p < 4; p++)
                #pragma unroll
                for (int mi = 0; mi < 2; mi++) {
                    mma_bf16(acc[mi][2 * p],     fah[mi], fbl[p]);
                    mma_bf16(acc[mi][2 * p + 1], fah[mi], fbl[p] + 2);
                }
            // Pass 3: lo*hi
            #pragma unroll
            for (int p = 0; p < 4; p++)
                #pragma unroll
                for (int mi = 0; mi < 2; mi++) {
                    mma_bf16(acc[mi][2 * p],     fal[mi], fbh[p]);
                    mma_bf16(acc[mi][2 * p + 1], fal[mi], fbh[p] + 2);
                }
        }

        if (it + 1 < iters) stage_store(cur ^ 1);
        __syncthreads();
    }

    // Epilogue. For split3: column n -> buffer (n>>10), col (n&1023).
    float* Cb = C;
    int ncols = N;
    int cbase = col0;
    if (split3) {
        Cb = C + (size_t)(col0 >> 10) * NB_ELEM;
        ncols = DMODEL;
        cbase = col0 & (DMODEL - 1);
    }
    #pragma unroll
    for (int mi = 0; mi < 2; mi++) {
        #pragma unroll
        for (int ni = 0; ni < 8; ni++) {
            int rg = row0 + wm * 32 + mi * 16 + g;
            int cg = cbase + wn * 64 + ni * 8 + tg * 2;
            *(float2*)&Cb[(size_t)rg * ncols + cg]       = make_float2(acc[mi][ni][0], acc[mi][ni][1]);
            *(float2*)&Cb[(size_t)(rg + 8) * ncols + cg] = make_float2(acc[mi][ni][2], acc[mi][ni][3]);
        }
    }
}

// ---------------------------------------------------------------------------
// In-place NeoX RoPE on Q and K
// ---------------------------------------------------------------------------
__global__ void rope_kernel(float* __restrict__ Q, float* __restrict__ K,
                            const int* __restrict__ positions) {
    int idx = blockIdx.x * blockDim.x + threadIdx.x;
    if (idx >= MROWS * NHEADS * 32) return;
    int d = idx & 31;
    int h = (idx >> 5) & 15;
    int m = idx >> 9;
    int s = m & (SEQ - 1);

    float pos = (float)positions[s];
    float inv_freq = exp2f((float)d * -0.4152410118609203f);
    float ang = pos * inv_freq;
    float c, sn;
    sincosf(ang, &sn, &c);

    size_t base = (size_t)m * DMODEL + h * DHEAD + d;
    float q1 = Q[base], q2 = Q[base + 32];
    Q[base]      = q1 * c - q2 * sn;
    Q[base + 32] = q2 * c + q1 * sn;
    float k1 = K[base], k2 = K[base + 32];
    K[base]      = k1 * c - k2 * sn;
    K[base + 32] = k2 * c + k1 * sn;
}

// ---------------------------------------------------------------------------
// Flash attention v3: fp16 m16n8k16 MMA, register-resident softmax (FA2).
// BQ=128, 8 warps x m16 (full n=64 per warp). BK=64. (unchanged from R7)
// ---------------------------------------------------------------------------
#define AST 66

__global__ __launch_bounds__(256, 2)
void attn3_kernel(const float* __restrict__ Q, const float* __restrict__ K,
                  const float* __restrict__ V, float* __restrict__ O) {
    __shared__ __half sh[128 * AST];
    __half* Qs = sh;
    __half* Kn = sh;                   // [key][d]
    __half* Vt = sh + 64 * AST;        // [d][key]

    const int tid  = threadIdx.x;
    const int lane = tid & 31;
    const int wid  = tid >> 5;
    const int g    = lane >> 2;
    const int tg   = lane & 3;
    const int m0   = wid * 16;

    const int bh = blockIdx.y;
    const int b  = bh >> 4;
    const int h  = bh & 15;
    const int q0 = blockIdx.x * 128;
    const size_t base = (size_t)b * SEQ * DMODEL + (size_t)h * DHEAD;

    {
        const int lr = tid >> 4;
        const int d4 = (tid & 15) * 4;
        #pragma unroll
        for (int i = 0; i < 8; i++) {
            int r = lr + i * 16;
            float4 qv = *(const float4*)&Q[base + (size_t)(q0 + r) * DMODEL + d4];
            *(uint32_t*)&Qs[r * AST + d4]     = packh2(qv.x, qv.y);
            *(uint32_t*)&Qs[r * AST + d4 + 2] = packh2(qv.z, qv.w);
        }
    }
    __syncthreads();

    uint32_t qa[4][4];
    #pragma unroll
    for (int kst = 0; kst < 4; kst++) {
        int ks = kst * 16 + 2 * tg;
        qa[kst][0] = *(uint32_t*)&Qs[(m0 + g) * AST + ks];
        qa[kst][1] = *(uint32_t*)&Qs[(m0 + g + 8) * AST + ks];
        qa[kst][2] = *(uint32_t*)&Qs[(m0 + g) * AST + ks + 8];
        qa[kst][3] = *(uint32_t*)&Qs[(m0 + g + 8) * AST + ks + 8];
    }

    float accO[8][4];
    #pragma unroll
    for (int i = 0; i < 8; i++)
        #pragma unroll
        for (int j = 0; j < 4; j++) accO[i][j] = 0.f;
    float mr0 = -INFINITY, mr1 = -INFINITY, lr0 = 0.f, lr1 = 0.f;

    for (int kt = 0; kt < SEQ; kt += 64) {
        __syncthreads();
        {
            const int lr = tid >> 4;
            const int d4 = (tid & 15) * 4;
            #pragma unroll
            for (int i = 0; i < 4; i++) {
                int r = lr + i * 16;
                float4 kv = *(const float4*)&K[base + (size_t)(kt + r) * DMODEL + d4];
                *(uint32_t*)&Kn[r * AST + d4]     = packh2(kv.x, kv.y);
                *(uint32_t*)&Kn[r * AST + d4 + 2] = packh2(kv.z, kv.w);
                float4 vv = *(const float4*)&V[base + (size_t)(kt + r) * DMODEL + d4];
                Vt[(d4 + 0) * AST + r] = __float2half_rn(vv.x);
                Vt[(d4 + 1) * AST + r] = __float2half_rn(vv.y);
                Vt[(d4 + 2) * AST + r] = __float2half_rn(vv.z);
                Vt[(d4 + 3) * AST + r] = __float2half_rn(vv.w);
            }
        }
        __syncthreads();

        float s[8][4];
        #pragma unroll
        for (int i = 0; i < 8; i++)
            #pragma unroll
            for (int j = 0; j < 4; j++) s[i][j] = 0.f;
        #pragma unroll
        for (int kst = 0; kst < 4; kst++) {
            int ks = kst * 16 + 2 * tg;
            #pragma unroll
            for (int ni = 0; ni < 8; ni++) {
                uint32_t bb[2];
                bb[0] = *(uint32_t*)&Kn[(ni * 8 + g) * AST + ks];
                bb[1] = *(uint32_t*)&Kn[(ni * 8 + g) * AST + ks + 8];
                mma_f16(s[ni], qa[kst], bb);
            }
        }

        float nm0 = mr0, nm1 = mr1;
        #pragma unroll
        for (int ni = 0; ni < 8; ni++) {
            nm0 = fmaxf(nm0, fmaxf(s[ni][0], s[ni][1]));
            nm1 = fmaxf(nm1, fmaxf(s[ni][2], s[ni][3]));
        }
        nm0 = fmaxf(nm0, __shfl_xor_sync(0xffffffffu, nm0, 1));
        nm0 = fmaxf(nm0, __shfl_xor_sync(0xffffffffu, nm0, 2));
        nm1 = fmaxf(nm1, __shfl_xor_sync(0xffffffffu, nm1, 1));
        nm1 = fmaxf(nm1, __shfl_xor_sync(0xffffffffu, nm1, 2));
        float a0 = __expf(mr0 - nm0);
        float a1 = __expf(mr1 - nm1);
        float sum0 = 0.f, sum1 = 0.f;
        #pragma unroll
        for (int ni = 0; ni < 8; ni++) {
            s[ni][0] = __expf(s[ni][0] - nm0); sum0 += s[ni][0];
            s[ni][1] = __expf(s[ni][1] - nm0); sum0 += s[ni][1];
            s[ni][2] = __expf(s[ni][2] - nm1); sum1 += s[ni][2];
            s[ni][3] = __expf(s[ni][3] - nm1); sum1 += s[ni][3];
        }
        sum0 += __shfl_xor_sync(0xffffffffu, sum0, 1);
        sum0 += __shfl_xor_sync(0xffffffffu, sum0, 2);
        sum1 += __shfl_xor_sync(0xffffffffu, sum1, 1);
        sum1 += __shfl_xor_sync(0xffffffffu, sum1, 2);
        lr0 = lr0 * a0 + sum0;
        lr1 = lr1 * a1 + sum1;
        mr0 = nm0; mr1 = nm1;

        #pragma unroll
        for (int ni = 0; ni < 8; ni++) {
            accO[ni][0] *= a0; accO[ni][1] *= a0;
            accO[ni][2] *= a1; accO[ni][3] *= a1;
        }

        #pragma unroll
        for (int kst = 0; kst < 4; kst++) {
            uint32_t pf[4];
            pf[0] = packh2(s[2 * kst][0],     s[2 * kst][1]);
            pf[1] = packh2(s[2 * kst][2],     s[2 * kst][3]);
            pf[2] = packh2(s[2 * kst + 1][0], s[2 * kst + 1][1]);
            pf[3] = packh2(s[2 * kst + 1][2], s[2 * kst + 1][3]);
            int ks = kst * 16 + 2 * tg;
            #pragma unroll
            for (int ni = 0; ni < 8; ni++) {
                uint32_t bb[2];
                bb[0] = *(uint32_t*)&Vt[(ni * 8 + g) * AST + ks];
                bb[1] = *(uint32_t*)&Vt[(ni * 8 + g) * AST + ks + 8];
                mma_f16(accO[ni], pf, bb);
            }
        }
    }

    {
        float i0 = 1.f / lr0;
        float i1 = 1.f / lr1;
        #pragma unroll
        for (int ni = 0; ni < 8; ni++) {
            int c = ni * 8 + 2 * tg;
            *(float2*)&O[base + (size_t)(q0 + m0 + g) * DMODEL + c] =
                make_float2(accO[ni][0] * i0, accO[ni][1] * i0);
            *(float2*)&O[base + (size_t)(q0 + m0 + g + 8) * DMODEL + c] =
                make_float2(accO[ni][2] * i1, accO[ni][3] * i1);
        }
    }
}

// ---------------------------------------------------------------------------
// Launch
// ---------------------------------------------------------------------------
extern "C" void kernel_launch(void* const* d_in, const int* in_sizes, int n_in,
                              void* d_out, int out_size) {
    const int*   positions = (const int*)d_in[0];
    const float* X  = (const float*)d_in[1];
    const float* wq = (const float*)d_in[2];
    const float* wk = (const float*)d_in[3];
    const float* wv = (const float*)d_in[4];
    const float* wo = (const float*)d_in[5];
    float* out = (float*)d_out;

    float* bufs = nullptr;
    cudaGetSymbolAddress((void**)&bufs, g_bufs);
    float* Qp = bufs;
    float* Kp = bufs + NB_ELEM;
    float* Vp = bufs + 2 * NB_ELEM;
    float* Op = bufs + 3 * NB_ELEM;

    __nv_bfloat16 *xh, *xl, *oh, *ol, *wht, *wlt;
    cudaGetSymbolAddress((void**)&xh, g_xh);
    cudaGetSymbolAddress((void**)&xl, g_xl);
    cudaGetSymbolAddress((void**)&oh, g_oh);
    cudaGetSymbolAddress((void**)&ol, g_ol);
    cudaGetSymbolAddress((void**)&wht, g_wht);
    cudaGetSymbolAddress((void**)&wlt, g_wlt);
    const size_t WSZ = (size_t)DMODEL * DMODEL;

    int n4 = (int)(NB_ELEM / 4);
    split_plain<<<(n4 + 255) / 256, 256>>>(X, xh, xl, n4);
    dim3 wtg(DMODEL / 32, DMODEL / 32), wtb(32, 8);
    split_wt<<<wtg, wtb>>>(wq, wht + 0 * WSZ, wlt + 0 * WSZ);
    split_wt<<<wtg, wtb>>>(wk, wht + 1 * WSZ, wlt + 1 * WSZ);
    split_wt<<<wtg, wtb>>>(wv, wht + 2 * WSZ, wlt + 2 * WSZ);
    split_wt<<<wtg, wtb>>>(wo, wht + 3 * WSZ, wlt + 3 * WSZ);

    cudaFuncSetAttribute(gemm_bf16s, cudaFuncAttributeMaxDynamicSharedMemorySize, GSMEM);
    // Fused QKV projection: N = 3072, epilogue splits into Qp/Kp/Vp (contiguous)
    dim3 fgrid(3 * DMODEL / 128, MROWS / 128);   // (24, 64)
    gemm_bf16s<<<fgrid, 256, GSMEM>>>(xh, xl, wht, wlt, Qp, MROWS, 3 * DMODEL, DMODEL, 1);

    int pairs = MROWS * NHEADS * 32;
    rope_kernel<<<(pairs + 255) / 256, 256>>>(Qp, Kp, positions);

    attn3_kernel<<<dim3(SEQ / 128, BATCH * NHEADS), 256>>>(Qp, Kp, Vp, Op);

    split_plain<<<(n4 + 255) / 256, 256>>>(Op, oh, ol, n4);
    dim3 ggrid(DMODEL / 128, MROWS / 128);       // (8, 64)
    gemm_bf16s<<<ggrid, 256, GSMEM>>>(oh, ol, wht + 3 * WSZ, wlt + 3 * WSZ, out, MROWS, DMODEL, DMODEL, 0);
}

// round 9
// speedup vs baseline: 2.6468x; 1.0636x over previous
#include <cuda_runtime.h>
#include <cuda_bf16.h>
#include <cuda_fp16.h>
#include <math.h>
#include <stdint.h>

// Problem constants
#define BATCH   4
#define SEQ     2048
#define DMODEL  1024
#define NHEADS  16
#define DHEAD   64
#define MROWS   (BATCH * SEQ)            // 8192
#define NB_ELEM ((size_t)MROWS * DMODEL)

#define LOSC 1024.0f                     // lo-part scale (avoids fp16 denormals)
#define ILOSC (1.0f / 1024.0f)

// fp32 scratch: Q, K, V projections + attention output (contiguous)
__device__ float g_bufs[4][MROWS * DMODEL];
// fp16 hi/lo pre-split buffers
__device__ __half g_xh[MROWS * DMODEL];
__device__ __half g_xl[MROWS * DMODEL];
__device__ __half g_oh[MROWS * DMODEL];
__device__ __half g_ol[MROWS * DMODEL];
__device__ __half g_wht[4][DMODEL * DMODEL];  // transposed [n][k], contiguous
__device__ __half g_wlt[4][DMODEL * DMODEL];

// ---------------------------------------------------------------------------
// Helpers
// ---------------------------------------------------------------------------
__device__ __forceinline__ uint32_t smem_u32(const void* p) {
    uint32_t a;
    asm("{ .reg .u64 t; cvta.to.shared.u64 t, %1; cvt.u32.u64 %0, t; }" : "=r"(a) : "l"(p));
    return a;
}
__device__ __forceinline__ void split_f16(float x, __half& h, __half& l) {
    h = __float2half_rn(x);
    l = __float2half_rn((x - __half2float(h)) * LOSC);
}
__device__ __forceinline__ uint32_t packh2h(__half a, __half b) {
    __half2 t = __halves2half2(a, b);
    return *reinterpret_cast<uint32_t*>(&t);
}
__device__ __forceinline__ uint32_t packh2(float a, float b) {
    __half2 t = __floats2half2_rn(a, b);
    return *reinterpret_cast<uint32_t*>(&t);
}
// fp32-accum fp16 MMA
__device__ __forceinline__ void mma_f16(float* c, const uint32_t* a, const uint32_t* b) {
    asm("mma.sync.aligned.m16n8k16.row.col.f32.f16.f16.f32 "
        "{%0,%1,%2,%3}, {%4,%5,%6,%7}, {%8,%9}, {%0,%1,%2,%3};"
        : "+f"(c[0]), "+f"(c[1]), "+f"(c[2]), "+f"(c[3])
        : "r"(a[0]), "r"(a[1]), "r"(a[2]), "r"(a[3]), "r"(b[0]), "r"(b[1]));
}
// fp16-accum fp16 MMA (2x rate path)
__device__ __forceinline__ void mma_f16h(uint32_t* c, const uint32_t* a, const uint32_t* b) {
    asm("mma.sync.aligned.m16n8k16.row.col.f16.f16.f16.f16 "
        "{%0,%1}, {%2,%3,%4,%5}, {%6,%7}, {%0,%1};"
        : "+r"(c[0]), "+r"(c[1])
        : "r"(a[0]), "r"(a[1]), "r"(a[2]), "r"(a[3]), "r"(b[0]), "r"(b[1]));
}
__device__ __forceinline__ void ldsm4(uint32_t* r, uint32_t addr) {
    asm volatile("ldmatrix.sync.aligned.m8n8.x4.shared.b16 {%0,%1,%2,%3}, [%4];"
                 : "=r"(r[0]), "=r"(r[1]), "=r"(r[2]), "=r"(r[3]) : "r"(addr));
}
__device__ __forceinline__ void cp16(uint32_t dst, const void* src) {
    asm volatile("cp.async.cg.shared.global [%0], [%1], 16;" :: "r"(dst), "l"(src));
}
__device__ __forceinline__ void cp_commit() {
    asm volatile("cp.async.commit_group;");
}

// ---------------------------------------------------------------------------
// Split fp32 -> fp16 hi/lo (same layout)
// ---------------------------------------------------------------------------
__global__ void split_plain(const float* __restrict__ X,
                            __half* __restrict__ H,
                            __half* __restrict__ L, int n4) {
    int i = blockIdx.x * blockDim.x + threadIdx.x;
    if (i >= n4) return;
    float4 v = ((const float4*)X)[i];
    __half h0,h1,h2,h3,l0,l1,l2,l3;
    split_f16(v.x, h0, l0); split_f16(v.y, h1, l1);
    split_f16(v.z, h2, l2); split_f16(v.w, h3, l3);
    ((uint2*)H)[i] = make_uint2(packh2h(h0,h1), packh2h(h2,h3));
    ((uint2*)L)[i] = make_uint2(packh2h(l0,l1), packh2h(l2,l3));
}

// ---------------------------------------------------------------------------
// Split + transpose weights: W[k][n] (1024x1024) -> Ht[n][k], Lt[n][k]
// ---------------------------------------------------------------------------
__global__ void split_wt(const float* __restrict__ W,
                         __half* __restrict__ Ht,
                         __half* __restrict__ Lt) {
    __shared__ float t[32][33];
    const int n0 = blockIdx.x * 32, k0 = blockIdx.y * 32;
    const int tx = threadIdx.x, ty = threadIdx.y;
    #pragma unroll
    for (int i = 0; i < 4; i++)
        t[ty + 8 * i][tx] = W[(size_t)(k0 + ty + 8 * i) * DMODEL + n0 + tx];
    __syncthreads();
    #pragma unroll
    for (int i = 0; i < 4; i++) {
        float v = t[tx][ty + 8 * i];
        __half h, l;
        split_f16(v, h, l);
        size_t o = (size_t)(n0 + ty + 8 * i) * DMODEL + k0 + tx;
        Ht[o] = h;
        Lt[o] = l;
    }
}

// ---------------------------------------------------------------------------
// fp16x2.5-split tensor-core GEMM, cp.async 3-stage pipeline.
// Pass 1: hi*hi (f32 accum). Passes 2,3: hi*lo', lo'*hi (fp16 accum, 2x rate),
// descale by 2^-10 at epilogue. C = A*B; A [m][k] hi/lo; B [n][k] hi/lo.
// CTA 128x128, BK=32, 256 threads (8 warps: 4m x 2n, warp tile 32x64).
// ---------------------------------------------------------------------------
#define RS   48
#define TSZ  (128 * RS * 2)          // 12288 bytes
#define SSTG (4 * TSZ)               // 49152
#define NSTG 3
#define GSMEM (NSTG * SSTG)          // 147456

__global__ __launch_bounds__(256)
void gemm_f16s(const __half* __restrict__ AH, const __half* __restrict__ AL,
               const __half* __restrict__ BHt, const __half* __restrict__ BLt,
               float* __restrict__ C, int M, int N, int K, int split3) {
    extern __shared__ char smem[];
    const uint32_t sb = smem_u32(smem);

    const int tid  = threadIdx.x;
    const int lane = tid & 31;
    const int wid  = tid >> 5;
    const int wm   = wid & 3;
    const int wn   = wid >> 2;
    const int g    = lane >> 2;
    const int tg   = lane & 3;
    const int row0 = blockIdx.y * 128;
    const int col0 = blockIdx.x * 128;

    const int am = tid >> 1;                // 0..127
    const int ak = (tid & 1) * 16;          // 0 or 16 (halves)
    const int bn = tid & 127;
    const int bk = (tid >> 7) * 16;

    const int arow  = wm * 32 + (lane & 15);
    const int akoff = (lane >> 4) * 8;
    const int brow  = wn * 64 + (lane & 7) + ((lane >> 4) << 3);
    const int bkoff = ((lane >> 3) & 1) * 8;

    float accf[2][8][4];
    uint32_t acch[2][8][2];
    #pragma unroll
    for (int i = 0; i < 2; i++)
        #pragma unroll
        for (int j = 0; j < 8; j++) {
            #pragma unroll
            for (int q = 0; q < 4; q++) accf[i][j][q] = 0.f;
            acch[i][j][0] = 0u; acch[i][j][1] = 0u;
        }

    // cp.async issue for one stage
    auto issue = [&](int it) {
        const int st = it % NSTG;
        const int kc = it * 32;
        uint32_t ahs = sb + st * SSTG +          (am * RS + ak) * 2;
        uint32_t als = ahs + TSZ;
        uint32_t bhs = sb + st * SSTG + 2 * TSZ + (bn * RS + bk) * 2;
        uint32_t bls = bhs + TSZ;
        size_t ab = (size_t)(row0 + am) * K + kc + ak;
        size_t bb = (size_t)(col0 + bn) * K + kc + bk;
        cp16(ahs,      &AH[ab]);     cp16(ahs + 16, &AH[ab + 8]);
        cp16(als,      &AL[ab]);     cp16(als + 16, &AL[ab + 8]);
        cp16(bhs,      &BHt[bb]);    cp16(bhs + 16, &BHt[bb + 8]);
        cp16(bls,      &BLt[bb]);    cp16(bls + 16, &BLt[bb + 8]);
        cp_commit();
    };

    const int iters = K / 32;   // 32
    issue(0);
    issue(1);

    for (int it = 0; it < iters; it++) {
        if (it == iters - 1)
            asm volatile("cp.async.wait_group 0;");
        else
            asm volatile("cp.async.wait_group 1;");
        __syncthreads();

        if (it + 2 < iters) issue(it + 2);

        const uint32_t base = sb + (it % NSTG) * SSTG;
        const uint32_t ahb = base;
        const uint32_t alb = base + TSZ;
        const uint32_t bhb = base + 2 * TSZ;
        const uint32_t blb = base + 3 * TSZ;

        #pragma unroll
        for (int ks = 0; ks < 32; ks += 16) {
            uint32_t fah[2][4], fal[2][4], fbh[4][4], fbl[4][4];
            #pragma unroll
            for (int mi = 0; mi < 2; mi++) {
                uint32_t off = (uint32_t)(((arow + mi * 16) * RS + ks + akoff) * 2);
                ldsm4(fah[mi], ahb + off);
                ldsm4(fal[mi], alb + off);
            }
            #pragma unroll
            for (int p = 0; p < 4; p++) {
                uint32_t off = (uint32_t)(((brow + p * 16) * RS + ks + bkoff) * 2);
                ldsm4(fbh[p], bhb + off);
                ldsm4(fbl[p], blb + off);
            }
            // Pass 1: hi*hi -> f32 accum
            #pragma unroll
            for (int p = 0; p < 4; p++)
                #pragma unroll
                for (int mi = 0; mi < 2; mi++) {
                    mma_f16(accf[mi][2 * p],     fah[mi], fbh[p]);
                    mma_f16(accf[mi][2 * p + 1], fah[mi], fbh[p] + 2);
                }
            // Passes 2+3: hi*lo' and lo'*hi -> shared fp16 accum (2x rate)
            #pragma unroll
            for (int p = 0; p < 4; p++)
                #pragma unroll
                for (int mi = 0; mi < 2; mi++) {
                    mma_f16h(acch[mi][2 * p],     fah[mi], fbl[p]);
                    mma_f16h(acch[mi][2 * p + 1], fah[mi], fbl[p] + 2);
                }
            #pragma unroll
            for (int p = 0; p < 4; p++)
                #pragma unroll
                for (int mi = 0; mi < 2; mi++) {
                    mma_f16h(acch[mi][2 * p],     fal[mi], fbh[p]);
                    mma_f16h(acch[mi][2 * p + 1], fal[mi], fbh[p] + 2);
                }
        }
        __syncthreads();
    }

    // Epilogue: combine f32 + descaled fp16 corrections.
    float* Cb = C;
    int ncols = N;
    int cbase = col0;
    if (split3) {
        Cb = C + (size_t)(col0 >> 10) * NB_ELEM;
        ncols = DMODEL;
        cbase = col0 & (DMODEL - 1);
    }
    #pragma unroll
    for (int mi = 0; mi < 2; mi++) {
        #pragma unroll
        for (int ni = 0; ni < 8; ni++) {
            __half2 h0 = *reinterpret_cast<__half2*>(&acch[mi][ni][0]);
            __half2 h1 = *reinterpret_cast<__half2*>(&acch[mi][ni][1]);
            float c0 = accf[mi][ni][0] + __low2float(h0)  * ILOSC;
            float c1 = accf[mi][ni][1] + __high2float(h0) * ILOSC;
            float c2 = accf[mi][ni][2] + __low2float(h1)  * ILOSC;
            float c3 = accf[mi][ni][3] + __high2float(h1) * ILOSC;
            int rg = row0 + wm * 32 + mi * 16 + g;
            int cg = cbase + wn * 64 + ni * 8 + tg * 2;
            *(float2*)&Cb[(size_t)rg * ncols + cg]       = make_float2(c0, c1);
            *(float2*)&Cb[(size_t)(rg + 8) * ncols + cg] = make_float2(c2, c3);
        }
    }
}

// ---------------------------------------------------------------------------
// In-place NeoX RoPE on Q and K
// ---------------------------------------------------------------------------
__global__ void rope_kernel(float* __restrict__ Q, float* __restrict__ K,
                            const int* __restrict__ positions) {
    int idx = blockIdx.x * blockDim.x + threadIdx.x;
    if (idx >= MROWS * NHEADS * 32) return;
    int d = idx & 31;
    int h = (idx >> 5) & 15;
    int m = idx >> 9;
    int s = m & (SEQ - 1);

    float pos = (float)positions[s];
    float inv_freq = exp2f((float)d * -0.4152410118609203f);
    float ang = pos * inv_freq;
    float c, sn;
    sincosf(ang, &sn, &c);

    size_t base = (size_t)m * DMODEL + h * DHEAD + d;
    float q1 = Q[base], q2 = Q[base + 32];
    Q[base]      = q1 * c - q2 * sn;
    Q[base + 32] = q2 * c + q1 * sn;
    float k1 = K[base], k2 = K[base + 32];
    K[base]      = k1 * c - k2 * sn;
    K[base + 32] = k2 * c + k1 * sn;
}

// ---------------------------------------------------------------------------
// Flash attention v3: fp16 m16n8k16 MMA, register-resident softmax (FA2).
// BQ=128, 8 warps x m16 (full n=64 per warp). BK=64. (unchanged)
// ---------------------------------------------------------------------------
#define AST 66

__global__ __launch_bounds__(256, 2)
void attn3_kernel(const float* __restrict__ Q, const float* __restrict__ K,
                  const float* __restrict__ V, float* __restrict__ O) {
    __shared__ __half sh[128 * AST];
    __half* Qs = sh;
    __half* Kn = sh;                   // [key][d]
    __half* Vt = sh + 64 * AST;        // [d][key]

    const int tid  = threadIdx.x;
    const int lane = tid & 31;
    const int wid  = tid >> 5;
    const int g    = lane >> 2;
    const int tg   = lane & 3;
    const int m0   = wid * 16;

    const int bh = blockIdx.y;
    const int b  = bh >> 4;
    const int h  = bh & 15;
    const int q0 = blockIdx.x * 128;
    const size_t base = (size_t)b * SEQ * DMODEL + (size_t)h * DHEAD;

    {
        const int lr = tid >> 4;
        const int d4 = (tid & 15) * 4;
        #pragma unroll
        for (int i = 0; i < 8; i++) {
            int r = lr + i * 16;
            float4 qv = *(const float4*)&Q[base + (size_t)(q0 + r) * DMODEL + d4];
            *(uint32_t*)&Qs[r * AST + d4]     = packh2(qv.x, qv.y);
            *(uint32_t*)&Qs[r * AST + d4 + 2] = packh2(qv.z, qv.w);
        }
    }
    __syncthreads();

    uint32_t qa[4][4];
    #pragma unroll
    for (int kst = 0; kst < 4; kst++) {
        int ks = kst * 16 + 2 * tg;
        qa[kst][0] = *(uint32_t*)&Qs[(m0 + g) * AST + ks];
        qa[kst][1] = *(uint32_t*)&Qs[(m0 + g + 8) * AST + ks];
        qa[kst][2] = *(uint32_t*)&Qs[(m0 + g) * AST + ks + 8];
        qa[kst][3] = *(uint32_t*)&Qs[(m0 + g + 8) * AST + ks + 8];
    }

    float accO[8][4];
    #pragma unroll
    for (int i = 0; i < 8; i++)
        #pragma unroll
        for (int j = 0; j < 4; j++) accO[i][j] = 0.f;
    float mr0 = -INFINITY, mr1 = -INFINITY, lr0 = 0.f, lr1 = 0.f;

    for (int kt = 0; kt < SEQ; kt += 64) {
        __syncthreads();
        {
            const int lr = tid >> 4;
            const int d4 = (tid & 15) * 4;
            #pragma unroll
            for (int i = 0; i < 4; i++) {
                int r = lr + i * 16;
                float4 kv = *(const float4*)&K[base + (size_t)(kt + r) * DMODEL + d4];
                *(uint32_t*)&Kn[r * AST + d4]     = packh2(kv.x, kv.y);
                *(uint32_t*)&Kn[r * AST + d4 + 2] = packh2(kv.z, kv.w);
                float4 vv = *(const float4*)&V[base + (size_t)(kt + r) * DMODEL + d4];
                Vt[(d4 + 0) * AST + r] = __float2half_rn(vv.x);
                Vt[(d4 + 1) * AST + r] = __float2half_rn(vv.y);
                Vt[(d4 + 2) * AST + r] = __float2half_rn(vv.z);
                Vt[(d4 + 3) * AST + r] = __float2half_rn(vv.w);
            }
        }
        __syncthreads();

        float s[8][4];
        #pragma unroll
        for (int i = 0; i < 8; i++)
            #pragma unroll
            for (int j = 0; j < 4; j++) s[i][j] = 0.f;
        #pragma unroll
        for (int kst = 0; kst < 4; kst++) {
            int ks = kst * 16 + 2 * tg;
            #pragma unroll
            for (int ni = 0; ni < 8; ni++) {
                uint32_t bb[2];
                bb[0] = *(uint32_t*)&Kn[(ni * 8 + g) * AST + ks];
                bb[1] = *(uint32_t*)&Kn[(ni * 8 + g) * AST + ks + 8];
                mma_f16(s[ni], qa[kst], bb);
            }
        }

        float nm0 = mr0, nm1 = mr1;
        #pragma unroll
        for (int ni = 0; ni < 8; ni++) {
            nm0 = fmaxf(nm0, fmaxf(s[ni][0], s[ni][1]));
            nm1 = fmaxf(nm1, fmaxf(s[ni][2], s[ni][3]));
        }
        nm0 = fmaxf(nm0, __shfl_xor_sync(0xffffffffu, nm0, 1));
        nm0 = fmaxf(nm0, __shfl_xor_sync(0xffffffffu, nm0, 2));
        nm1 = fmaxf(nm1, __shfl_xor_sync(0xffffffffu, nm1, 1));
        nm1 = fmaxf(nm1, __shfl_xor_sync(0xffffffffu, nm1, 2));
        float a0 = __expf(mr0 - nm0);
        float a1 = __expf(mr1 - nm1);
        float sum0 = 0.f, sum1 = 0.f;
        #pragma unroll
        for (int ni = 0; ni < 8; ni++) {
            s[ni][0] = __expf(s[ni][0] - nm0); sum0 += s[ni][0];
            s[ni][1] = __expf(s[ni][1] - nm0); sum0 += s[ni][1];
            s[ni][2] = __expf(s[ni][2] - nm1); sum1 += s[ni][2];
            s[ni][3] = __expf(s[ni][3] - nm1); sum1 += s[ni][3];
        }
        sum0 += __shfl_xor_sync(0xffffffffu, sum0, 1);
        sum0 += __shfl_xor_sync(0xffffffffu, sum0, 2);
        sum1 += __shfl_xor_sync(0xffffffffu, sum1, 1);
        sum1 += __shfl_xor_sync(0xffffffffu, sum1, 2);
        lr0 = lr0 * a0 + sum0;
        lr1 = lr1 * a1 + sum1;
        mr0 = nm0; mr1 = nm1;

        #pragma unroll
        for (int ni = 0; ni < 8; ni++) {
            accO[ni][0] *= a0; accO[ni][1] *= a0;
            accO[ni][2] *= a1; accO[ni][3] *= a1;
        }

        #pragma unroll
        for (int kst = 0; kst < 4; kst++) {
            uint32_t pf[4];
            pf[0] = packh2(s[2 * kst][0],     s[2 * kst][1]);
            pf[1] = packh2(s[2 * kst][2],     s[2 * kst][3]);
            pf[2] = packh2(s[2 * kst + 1][0], s[2 * kst + 1][1]);
            pf[3] = packh2(s[2 * kst + 1][2], s[2 * kst + 1][3]);
            int ks = kst * 16 + 2 * tg;
            #pragma unroll
            for (int ni = 0; ni < 8; ni++) {
                uint32_t bb[2];
                bb[0] = *(uint32_t*)&Vt[(ni * 8 + g) * AST + ks];
                bb[1] = *(uint32_t*)&Vt[(ni * 8 + g) * AST + ks + 8];
                mma_f16(accO[ni], pf, bb);
            }
        }
    }

    {
        float i0 = 1.f / lr0;
        float i1 = 1.f / lr1;
        #pragma unroll
        for (int ni = 0; ni < 8; ni++) {
            int c = ni * 8 + 2 * tg;
            *(float2*)&O[base + (size_t)(q0 + m0 + g) * DMODEL + c] =
                make_float2(accO[ni][0] * i0, accO[ni][1] * i0);
            *(float2*)&O[base + (size_t)(q0 + m0 + g + 8) * DMODEL + c] =
                make_float2(accO[ni][2] * i1, accO[ni][3] * i1);
        }
    }
}

// ---------------------------------------------------------------------------
// Launch
// ---------------------------------------------------------------------------
extern "C" void kernel_launch(void* const* d_in, const int* in_sizes, int n_in,
                              void* d_out, int out_size) {
    const int*   positions = (const int*)d_in[0];
    const float* X  = (const float*)d_in[1];
    const float* wq = (const float*)d_in[2];
    const float* wk = (const float*)d_in[3];
    const float* wv = (const float*)d_in[4];
    const float* wo = (const float*)d_in[5];
    float* out = (float*)d_out;

    float* bufs = nullptr;
    cudaGetSymbolAddress((void**)&bufs, g_bufs);
    float* Qp = bufs;
    float* Kp = bufs + NB_ELEM;
    float* Vp = bufs + 2 * NB_ELEM;
    float* Op = bufs + 3 * NB_ELEM;

    __half *xh, *xl, *oh, *ol, *wht, *wlt;
    cudaGetSymbolAddress((void**)&xh, g_xh);
    cudaGetSymbolAddress((void**)&xl, g_xl);
    cudaGetSymbolAddress((void**)&oh, g_oh);
    cudaGetSymbolAddress((void**)&ol, g_ol);
    cudaGetSymbolAddress((void**)&wht, g_wht);
    cudaGetSymbolAddress((void**)&wlt, g_wlt);
    const size_t WSZ = (size_t)DMODEL * DMODEL;

    int n4 = (int)(NB_ELEM / 4);
    split_plain<<<(n4 + 255) / 256, 256>>>(X, xh, xl, n4);
    dim3 wtg(DMODEL / 32, DMODEL / 32), wtb(32, 8);
    split_wt<<<wtg, wtb>>>(wq, wht + 0 * WSZ, wlt + 0 * WSZ);
    split_wt<<<wtg, wtb>>>(wk, wht + 1 * WSZ, wlt + 1 * WSZ);
    split_wt<<<wtg, wtb>>>(wv, wht + 2 * WSZ, wlt + 2 * WSZ);
    split_wt<<<wtg, wtb>>>(wo, wht + 3 * WSZ, wlt + 3 * WSZ);

    cudaFuncSetAttribute(gemm_f16s, cudaFuncAttributeMaxDynamicSharedMemorySize, GSMEM);
    // Fused QKV projection: N = 3072, epilogue splits into Qp/Kp/Vp
    dim3 fgrid(3 * DMODEL / 128, MROWS / 128);   // (24, 64)
    gemm_f16s<<<fgrid, 256, GSMEM>>>(xh, xl, wht, wlt, Qp, MROWS, 3 * DMODEL, DMODEL, 1);

    int pairs = MROWS * NHEADS * 32;
    rope_kernel<<<(pairs + 255) / 256, 256>>>(Qp, Kp, positions);

    attn3_kernel<<<dim3(SEQ / 128, BATCH * NHEADS), 256>>>(Qp, Kp, Vp, Op);

    split_plain<<<(n4 + 255) / 256, 256>>>(Op, oh, ol, n4);
    dim3 ggrid(DMODEL / 128, MROWS / 128);       // (8, 64)
    gemm_f16s<<<ggrid, 256, GSMEM>>>(oh, ol, wht + 3 * WSZ, wlt + 3 * WSZ, out, MROWS, DMODEL, DMODEL, 0);
}

// round 10
// speedup vs baseline: 3.1358x; 1.1847x over previous
#include <cuda_runtime.h>
#include <cuda_bf16.h>
#include <cuda_fp16.h>
#include <math.h>
#include <stdint.h>

// Problem constants
#define BATCH   4
#define SEQ     2048
#define DMODEL  1024
#define NHEADS  16
#define DHEAD   64
#define MROWS   (BATCH * SEQ)            // 8192
#define NB_ELEM ((size_t)MROWS * DMODEL)

#define LOSC 1024.0f                     // lo-part scale (avoids fp16 denormals)
#define ILOSC (1.0f / 1024.0f)

// fp16 pipeline buffers
__device__ __half g_qh[MROWS * DMODEL];       // Q post-rope, fp16
__device__ __half g_kh[MROWS * DMODEL];       // K post-rope, fp16
__device__ __half g_vh[MROWS * DMODEL];       // V, fp16
__device__ __half g_xh[MROWS * DMODEL];
__device__ __half g_xl[MROWS * DMODEL];
__device__ __half g_oh[MROWS * DMODEL];       // attention out hi
__device__ __half g_ol[MROWS * DMODEL];       // attention out lo (scaled)
__device__ __half g_wht[4][DMODEL * DMODEL];  // weights transposed [n][k]
__device__ __half g_wlt[4][DMODEL * DMODEL];

// ---------------------------------------------------------------------------
// Helpers
// ---------------------------------------------------------------------------
__device__ __forceinline__ uint32_t smem_u32(const void* p) {
    uint32_t a;
    asm("{ .reg .u64 t; cvta.to.shared.u64 t, %1; cvt.u32.u64 %0, t; }" : "=r"(a) : "l"(p));
    return a;
}
__device__ __forceinline__ void split_f16(float x, __half& h, __half& l) {
    h = __float2half_rn(x);
    l = __float2half_rn((x - __half2float(h)) * LOSC);
}
__device__ __forceinline__ uint32_t packh2h(__half a, __half b) {
    __half2 t = __halves2half2(a, b);
    return *reinterpret_cast<uint32_t*>(&t);
}
__device__ __forceinline__ uint32_t packh2(float a, float b) {
    __half2 t = __floats2half2_rn(a, b);
    return *reinterpret_cast<uint32_t*>(&t);
}
__device__ __forceinline__ void mma_f16(float* c, const uint32_t* a, const uint32_t* b) {
    asm("mma.sync.aligned.m16n8k16.row.col.f32.f16.f16.f32 "
        "{%0,%1,%2,%3}, {%4,%5,%6,%7}, {%8,%9}, {%0,%1,%2,%3};"
        : "+f"(c[0]), "+f"(c[1]), "+f"(c[2]), "+f"(c[3])
        : "r"(a[0]), "r"(a[1]), "r"(a[2]), "r"(a[3]), "r"(b[0]), "r"(b[1]));
}
__device__ __forceinline__ void mma_f16h(uint32_t* c, const uint32_t* a, const uint32_t* b) {
    asm("mma.sync.aligned.m16n8k16.row.col.f16.f16.f16.f16 "
        "{%0,%1}, {%2,%3,%4,%5}, {%6,%7}, {%0,%1};"
        : "+r"(c[0]), "+r"(c[1])
        : "r"(a[0]), "r"(a[1]), "r"(a[2]), "r"(a[3]), "r"(b[0]), "r"(b[1]));
}
__device__ __forceinline__ void ldsm4(uint32_t* r, uint32_t addr) {
    asm volatile("ldmatrix.sync.aligned.m8n8.x4.shared.b16 {%0,%1,%2,%3}, [%4];"
                 : "=r"(r[0]), "=r"(r[1]), "=r"(r[2]), "=r"(r[3]) : "r"(addr));
}
__device__ __forceinline__ void cp16(uint32_t dst, const void* src) {
    asm volatile("cp.async.cg.shared.global [%0], [%1], 16;" :: "r"(dst), "l"(src));
}
__device__ __forceinline__ void cp_commit() {
    asm volatile("cp.async.commit_group;");
}

// ---------------------------------------------------------------------------
// Split fp32 -> fp16 hi/lo
// ---------------------------------------------------------------------------
__global__ void split_plain(const float* __restrict__ X,
                            __half* __restrict__ H,
                            __half* __restrict__ L, int n4) {
    int i = blockIdx.x * blockDim.x + threadIdx.x;
    if (i >= n4) return;
    float4 v = ((const float4*)X)[i];
    __half h0,h1,h2,h3,l0,l1,l2,l3;
    split_f16(v.x, h0, l0); split_f16(v.y, h1, l1);
    split_f16(v.z, h2, l2); split_f16(v.w, h3, l3);
    ((uint2*)H)[i] = make_uint2(packh2h(h0,h1), packh2h(h2,h3));
    ((uint2*)L)[i] = make_uint2(packh2h(l0,l1), packh2h(l2,l3));
}

// ---------------------------------------------------------------------------
// Split + transpose weights: W[k][n] -> Ht[n][k], Lt[n][k]
// ---------------------------------------------------------------------------
__global__ void split_wt(const float* __restrict__ W,
                         __half* __restrict__ Ht,
                         __half* __restrict__ Lt) {
    __shared__ float t[32][33];
    const int n0 = blockIdx.x * 32, k0 = blockIdx.y * 32;
    const int tx = threadIdx.x, ty = threadIdx.y;
    #pragma unroll
    for (int i = 0; i < 4; i++)
        t[ty + 8 * i][tx] = W[(size_t)(k0 + ty + 8 * i) * DMODEL + n0 + tx];
    __syncthreads();
    #pragma unroll
    for (int i = 0; i < 4; i++) {
        float v = t[tx][ty + 8 * i];
        __half h, l;
        split_f16(v, h, l);
        size_t o = (size_t)(n0 + ty + 8 * i) * DMODEL + k0 + tx;
        Ht[o] = h;
        Lt[o] = l;
    }
}

// ---------------------------------------------------------------------------
// fp16-split tensor-core GEMM, cp.async 3-stage pipeline.
// mode 0: C_f32 = A*B  (final output projection)
// mode 1: fused QKV — N=3072; epilogue applies NeoX RoPE to Q,K and writes
//         fp16 to Qh/Kh/Vh (buffer = col0>>10).
// ---------------------------------------------------------------------------
#define RS   48
#define TSZ  (128 * RS * 2)          // 12288 bytes
#define SSTG (4 * TSZ)               // 49152
#define NSTG 3
#define GSMEM (NSTG * SSTG)          // 147456

__global__ __launch_bounds__(256)
void gemm_f16s(const __half* __restrict__ AH, const __half* __restrict__ AL,
               const __half* __restrict__ BHt, const __half* __restrict__ BLt,
               float* __restrict__ C, __half* __restrict__ QH,
               __half* __restrict__ KH, __half* __restrict__ VH,
               const int* __restrict__ positions,
               int M, int N, int K, int mode) {
    extern __shared__ char smem[];
    const uint32_t sb = smem_u32(smem);

    const int tid  = threadIdx.x;
    const int lane = tid & 31;
    const int wid  = tid >> 5;
    const int wm   = wid & 3;
    const int wn   = wid >> 2;
    const int g    = lane >> 2;
    const int tg   = lane & 3;
    const int row0 = blockIdx.y * 128;
    const int col0 = blockIdx.x * 128;

    const int am = tid >> 1;
    const int ak = (tid & 1) * 16;
    const int bn = tid & 127;
    const int bk = (tid >> 7) * 16;

    const int arow  = wm * 32 + (lane & 15);
    const int akoff = (lane >> 4) * 8;
    const int brow  = wn * 64 + (lane & 7) + ((lane >> 4) << 3);
    const int bkoff = ((lane >> 3) & 1) * 8;

    float accf[2][8][4];
    uint32_t acch[2][8][2];
    #pragma unroll
    for (int i = 0; i < 2; i++)
        #pragma unroll
        for (int j = 0; j < 8; j++) {
            #pragma unroll
            for (int q = 0; q < 4; q++) accf[i][j][q] = 0.f;
            acch[i][j][0] = 0u; acch[i][j][1] = 0u;
        }

    auto issue = [&](int it) {
        const int st = it % NSTG;
        const int kc = it * 32;
        uint32_t ahs = sb + st * SSTG +          (am * RS + ak) * 2;
        uint32_t als = ahs + TSZ;
        uint32_t bhs = sb + st * SSTG + 2 * TSZ + (bn * RS + bk) * 2;
        uint32_t bls = bhs + TSZ;
        size_t ab = (size_t)(row0 + am) * K + kc + ak;
        size_t bb = (size_t)(col0 + bn) * K + kc + bk;
        cp16(ahs,      &AH[ab]);     cp16(ahs + 16, &AH[ab + 8]);
        cp16(als,      &AL[ab]);     cp16(als + 16, &AL[ab + 8]);
        cp16(bhs,      &BHt[bb]);    cp16(bhs + 16, &BHt[bb + 8]);
        cp16(bls,      &BLt[bb]);    cp16(bls + 16, &BLt[bb + 8]);
        cp_commit();
    };

    const int iters = K / 32;
    issue(0);
    issue(1);

    for (int it = 0; it < iters; it++) {
        if (it == iters - 1)
            asm volatile("cp.async.wait_group 0;");
        else
            asm volatile("cp.async.wait_group 1;");
        __syncthreads();

        if (it + 2 < iters) issue(it + 2);

        const uint32_t base = sb + (it % NSTG) * SSTG;
        const uint32_t ahb = base;
        const uint32_t alb = base + TSZ;
        const uint32_t bhb = base + 2 * TSZ;
        const uint32_t blb = base + 3 * TSZ;

        #pragma unroll
        for (int ks = 0; ks < 32; ks += 16) {
            uint32_t fah[2][4], fal[2][4], fbh[4][4], fbl[4][4];
            #pragma unroll
            for (int mi = 0; mi < 2; mi++) {
                uint32_t off = (uint32_t)(((arow + mi * 16) * RS + ks + akoff) * 2);
                ldsm4(fah[mi], ahb + off);
                ldsm4(fal[mi], alb + off);
            }
            #pragma unroll
            for (int p = 0; p < 4; p++) {
                uint32_t off = (uint32_t)(((brow + p * 16) * RS + ks + bkoff) * 2);
                ldsm4(fbh[p], bhb + off);
                ldsm4(fbl[p], blb + off);
            }
            #pragma unroll
            for (int p = 0; p < 4; p++)
                #pragma unroll
                for (int mi = 0; mi < 2; mi++) {
                    mma_f16(accf[mi][2 * p],     fah[mi], fbh[p]);
                    mma_f16(accf[mi][2 * p + 1], fah[mi], fbh[p] + 2);
                }
            #pragma unroll
            for (int p = 0; p < 4; p++)
                #pragma unroll
                for (int mi = 0; mi < 2; mi++) {
                    mma_f16h(acch[mi][2 * p],     fah[mi], fbl[p]);
                    mma_f16h(acch[mi][2 * p + 1], fah[mi], fbl[p] + 2);
                }
            #pragma unroll
            for (int p = 0; p < 4; p++)
                #pragma unroll
                for (int mi = 0; mi < 2; mi++) {
                    mma_f16h(acch[mi][2 * p],     fal[mi], fbh[p]);
                    mma_f16h(acch[mi][2 * p + 1], fal[mi], fbh[p] + 2);
                }
        }
        __syncthreads();
    }

    // Combine f32 + descaled fp16 corrections into accf
    #pragma unroll
    for (int mi = 0; mi < 2; mi++)
        #pragma unroll
        for (int ni = 0; ni < 8; ni++) {
            __half2 h0 = *reinterpret_cast<__half2*>(&acch[mi][ni][0]);
            __half2 h1 = *reinterpret_cast<__half2*>(&acch[mi][ni][1]);
            accf[mi][ni][0] += __low2float(h0)  * ILOSC;
            accf[mi][ni][1] += __high2float(h0) * ILOSC;
            accf[mi][ni][2] += __low2float(h1)  * ILOSC;
            accf[mi][ni][3] += __high2float(h1) * ILOSC;
        }

    if (mode == 0) {
        #pragma unroll
        for (int mi = 0; mi < 2; mi++)
            #pragma unroll
            for (int ni = 0; ni < 8; ni++) {
                int rg = row0 + wm * 32 + mi * 16 + g;
                int cg = col0 + wn * 64 + ni * 8 + tg * 2;
                *(float2*)&C[(size_t)rg * N + cg]       = make_float2(accf[mi][ni][0], accf[mi][ni][1]);
                *(float2*)&C[(size_t)(rg + 8) * N + cg] = make_float2(accf[mi][ni][2], accf[mi][ni][3]);
            }
        return;
    }

    // mode 1: fused QKV epilogue. buffer 0=Q,1=K,2=V; rope on Q,K.
    const int buf = col0 >> 10;
    __half* dst = (buf == 0) ? QH : (buf == 1) ? KH : VH;
    const int colb0 = (col0 & (DMODEL - 1)) + wn * 64;

    if (buf < 2) {
        // NeoX rope: cols d = ni*8+tg*2+q (ni<4 -> d<32) pair with ni+4 (d+32).
        #pragma unroll
        for (int mi = 0; mi < 2; mi++) {
            int rg = row0 + wm * 32 + mi * 16 + g;
            float p0 = (float)positions[rg & (SEQ - 1)];
            float p1 = (float)positions[(rg + 8) & (SEQ - 1)];
            #pragma unroll
            for (int ni = 0; ni < 4; ni++) {
                #pragma unroll
                for (int q = 0; q < 2; q++) {
                    int d = ni * 8 + tg * 2 + q;
                    float invf = exp2f((float)d * -0.4152410118609203f);
                    float c0, s0, c1, s1;
                    sincosf(p0 * invf, &s0, &c0);
                    sincosf(p1 * invf, &s1, &c1);
                    float x1 = accf[mi][ni][q],     x2 = accf[mi][ni + 4][q];
                    accf[mi][ni][q]         = x1 * c0 - x2 * s0;
                    accf[mi][ni + 4][q]     = x2 * c0 + x1 * s0;
                    float y1 = accf[mi][ni][q + 2], y2 = accf[mi][ni + 4][q + 2];
                    accf[mi][ni][q + 2]     = y1 * c1 - y2 * s1;
                    accf[mi][ni + 4][q + 2] = y2 * c1 + y1 * s1;
                }
            }
        }
    }
    #pragma unroll
    for (int mi = 0; mi < 2; mi++)
        #pragma unroll
        for (int ni = 0; ni < 8; ni++) {
            int rg = row0 + wm * 32 + mi * 16 + g;
            int cg = colb0 + ni * 8 + tg * 2;
            *(uint32_t*)&dst[(size_t)rg * DMODEL + cg] =
                packh2(accf[mi][ni][0], accf[mi][ni][1]);
            *(uint32_t*)&dst[(size_t)(rg + 8) * DMODEL + cg] =
                packh2(accf[mi][ni][2], accf[mi][ni][3]);
        }
}

// ---------------------------------------------------------------------------
// Flash attention v4: fp16 inputs, fp16 m16n8k16 MMA, register softmax,
// emits hi/lo fp16 split of O directly. BQ=128, 8 warps x m16, BK=64.
// ---------------------------------------------------------------------------
#define AST 72   // smem row stride (halves): 144B, 16B-aligned, conflict-free

__global__ __launch_bounds__(256, 2)
void attn4_kernel(const __half* __restrict__ Q, const __half* __restrict__ K,
                  const __half* __restrict__ V,
                  __half* __restrict__ OH, __half* __restrict__ OL) {
    __shared__ __half sh[128 * AST];
    __half* Qs = sh;
    __half* Kn = sh;                   // [key][d]
    __half* Vt = sh + 64 * AST;        // [d][key]

    const int tid  = threadIdx.x;
    const int lane = tid & 31;
    const int wid  = tid >> 5;
    const int g    = lane >> 2;
    const int tg   = lane & 3;
    const int m0   = wid * 16;

    const int bh = blockIdx.y;
    const int b  = bh >> 4;
    const int h  = bh & 15;
    const int q0 = blockIdx.x * 128;
    const size_t base = (size_t)b * SEQ * DMODEL + (size_t)h * DHEAD;

    const int qr = tid >> 3;          // 0..31
    const int d8 = (tid & 7) * 8;     // 0..56

    // Prologue: Q tile (fp16, direct copy)
    #pragma unroll
    for (int i = 0; i < 4; i++) {
        int r = qr + 32 * i;
        *(uint4*)&Qs[r * AST + d8] =
            *(const uint4*)&Q[base + (size_t)(q0 + r) * DMODEL + d8];
    }
    __syncthreads();

    uint32_t qa[4][4];
    #pragma unroll
    for (int kst = 0; kst < 4; kst++) {
        int ks = kst * 16 + 2 * tg;
        qa[kst][0] = *(uint32_t*)&Qs[(m0 + g) * AST + ks];
        qa[kst][1] = *(uint32_t*)&Qs[(m0 + g + 8) * AST + ks];
        qa[kst][2] = *(uint32_t*)&Qs[(m0 + g) * AST + ks + 8];
        qa[kst][3] = *(uint32_t*)&Qs[(m0 + g + 8) * AST + ks + 8];
    }

    float accO[8][4];
    #pragma unroll
    for (int i = 0; i < 8; i++)
        #pragma unroll
        for (int j = 0; j < 4; j++) accO[i][j] = 0.f;
    float mr0 = -INFINITY, mr1 = -INFINITY, lr0 = 0.f, lr1 = 0.f;

    for (int kt = 0; kt < SEQ; kt += 64) {
        __syncthreads();
        #pragma unroll
        for (int i = 0; i < 2; i++) {
            int r = qr + 32 * i;
            *(uint4*)&Kn[r * AST + d8] =
                *(const uint4*)&K[base + (size_t)(kt + r) * DMODEL + d8];
            uint4 vv = *(const uint4*)&V[base + (size_t)(kt + r) * DMODEL + d8];
            const __half* vp = (const __half*)&vv;
            #pragma unroll
            for (int j = 0; j < 8; j++)
                Vt[(d8 + j) * AST + r] = vp[j];
        }
        __syncthreads();

        float s[8][4];
        #pragma unroll
        for (int i = 0; i < 8; i++)
            #pragma unroll
            for (int j = 0; j < 4; j++) s[i][j] = 0.f;
        #pragma unroll
        for (int kst = 0; kst < 4; kst++) {
            int ks = kst * 16 + 2 * tg;
            #pragma unroll
            for (int ni = 0; ni < 8; ni++) {
                uint32_t bb[2];
                bb[0] = *(uint32_t*)&Kn[(ni * 8 + g) * AST + ks];
                bb[1] = *(uint32_t*)&Kn[(ni * 8 + g) * AST + ks + 8];
                mma_f16(s[ni], qa[kst], bb);
            }
        }

        float nm0 = mr0, nm1 = mr1;
        #pragma unroll
        for (int ni = 0; ni < 8; ni++) {
            nm0 = fmaxf(nm0, fmaxf(s[ni][0], s[ni][1]));
            nm1 = fmaxf(nm1, fmaxf(s[ni][2], s[ni][3]));
        }
        nm0 = fmaxf(nm0, __shfl_xor_sync(0xffffffffu, nm0, 1));
        nm0 = fmaxf(nm0, __shfl_xor_sync(0xffffffffu, nm0, 2));
        nm1 = fmaxf(nm1, __shfl_xor_sync(0xffffffffu, nm1, 1));
        nm1 = fmaxf(nm1, __shfl_xor_sync(0xffffffffu, nm1, 2));
        float a0 = __expf(mr0 - nm0);
        float a1 = __expf(mr1 - nm1);
        float sum0 = 0.f, sum1 = 0.f;
        #pragma unroll
        for (int ni = 0; ni < 8; ni++) {
            s[ni][0] = __expf(s[ni][0] - nm0); sum0 += s[ni][0];
            s[ni][1] = __expf(s[ni][1] - nm0); sum0 += s[ni][1];
            s[ni][2] = __expf(s[ni][2] - nm1); sum1 += s[ni][2];
            s[ni][3] = __expf(s[ni][3] - nm1); sum1 += s[ni][3];
        }
        sum0 += __shfl_xor_sync(0xffffffffu, sum0, 1);
        sum0 += __shfl_xor_sync(0xffffffffu, sum0, 2);
        sum1 += __shfl_xor_sync(0xffffffffu, sum1, 1);
        sum1 += __shfl_xor_sync(0xffffffffu, sum1, 2);
        lr0 = lr0 * a0 + sum0;
        lr1 = lr1 * a1 + sum1;
        mr0 = nm0; mr1 = nm1;

        #pragma unroll
        for (int ni = 0; ni < 8; ni++) {
            accO[ni][0] *= a0; accO[ni][1] *= a0;
            accO[ni][2] *= a1; accO[ni][3] *= a1;
        }

        #pragma unroll
        for (int kst = 0; kst < 4; kst++) {
            uint32_t pf[4];
            pf[0] = packh2(s[2 * kst][0],     s[2 * kst][1]);
            pf[1] = packh2(s[2 * kst][2],     s[2 * kst][3]);
            pf[2] = packh2(s[2 * kst + 1][0], s[2 * kst + 1][1]);
            pf[3] = packh2(s[2 * kst + 1][2], s[2 * kst + 1][3]);
            int ks = kst * 16 + 2 * tg;
            #pragma unroll
            for (int ni = 0; ni < 8; ni++) {
                uint32_t bb[2];
                bb[0] = *(uint32_t*)&Vt[(ni * 8 + g) * AST + ks];
                bb[1] = *(uint32_t*)&Vt[(ni * 8 + g) * AST + ks + 8];
                mma_f16(accO[ni], pf, bb);
            }
        }
    }

    // Epilogue: normalize, split hi/lo fp16, store
    {
        float i0 = 1.f / lr0;
        float i1 = 1.f / lr1;
        size_t r0 = base + (size_t)(q0 + m0 + g) * DMODEL;
        size_t r1 = base + (size_t)(q0 + m0 + g + 8) * DMODEL;
        #pragma unroll
        for (int ni = 0; ni < 8; ni++) {
            int c = ni * 8 + 2 * tg;
            float v00 = accO[ni][0] * i0, v01 = accO[ni][1] * i0;
            float v10 = accO[ni][2] * i1, v11 = accO[ni][3] * i1;
            __half h00, l00, h01, l01, h10, l10, h11, l11;
            split_f16(v00, h00, l00); split_f16(v01, h01, l01);
            split_f16(v10, h10, l10); split_f16(v11, h11, l11);
            *(uint32_t*)&OH[r0 + c] = packh2h(h00, h01);
            *(uint32_t*)&OL[r0 + c] = packh2h(l00, l01);
            *(uint32_t*)&OH[r1 + c] = packh2h(h10, h11);
            *(uint32_t*)&OL[r1 + c] = packh2h(l10, l11);
        }
    }
}

// ---------------------------------------------------------------------------
// Launch
// ---------------------------------------------------------------------------
extern "C" void kernel_launch(void* const* d_in, const int* in_sizes, int n_in,
                              void* d_out, int out_size) {
    const int*   positions = (const int*)d_in[0];
    const float* X  = (const float*)d_in[1];
    const float* wq = (const float*)d_in[2];
    const float* wk = (const float*)d_in[3];
    const float* wv = (const float*)d_in[4];
    const float* wo = (const float*)d_in[5];
    float* out = (float*)d_out;

    __half *qh, *kh, *vh, *xh, *xl, *oh, *ol, *wht, *wlt;
    cudaGetSymbolAddress((void**)&qh, g_qh);
    cudaGetSymbolAddress((void**)&kh, g_kh);
    cudaGetSymbolAddress((void**)&vh, g_vh);
    cudaGetSymbolAddress((void**)&xh, g_xh);
    cudaGetSymbolAddress((void**)&xl, g_xl);
    cudaGetSymbolAddress((void**)&oh, g_oh);
    cudaGetSymbolAddress((void**)&ol, g_ol);
    cudaGetSymbolAddress((void**)&wht, g_wht);
    cudaGetSymbolAddress((void**)&wlt, g_wlt);
    const size_t WSZ = (size_t)DMODEL * DMODEL;

    int n4 = (int)(NB_ELEM / 4);
    split_plain<<<(n4 + 255) / 256, 256>>>(X, xh, xl, n4);
    dim3 wtg(DMODEL / 32, DMODEL / 32), wtb(32, 8);
    split_wt<<<wtg, wtb>>>(wq, wht + 0 * WSZ, wlt + 0 * WSZ);
    split_wt<<<wtg, wtb>>>(wk, wht + 1 * WSZ, wlt + 1 * WSZ);
    split_wt<<<wtg, wtb>>>(wv, wht + 2 * WSZ, wlt + 2 * WSZ);
    split_wt<<<wtg, wtb>>>(wo, wht + 3 * WSZ, wlt + 3 * WSZ);

    cudaFuncSetAttribute(gemm_f16s, cudaFuncAttributeMaxDynamicSharedMemorySize, GSMEM);
    // Fused QKV projection with in-epilogue RoPE, fp16 outputs
    dim3 fgrid(3 * DMODEL / 128, MROWS / 128);   // (24, 64)
    gemm_f16s<<<fgrid, 256, GSMEM>>>(xh, xl, wht, wlt,
                                     nullptr, qh, kh, vh, positions,
                                     MROWS, 3 * DMODEL, DMODEL, 1);

    attn4_kernel<<<dim3(SEQ / 128, BATCH * NHEADS), 256>>>(qh, kh, vh, oh, ol);

    dim3 ggrid(DMODEL / 128, MROWS / 128);       // (8, 64)
    gemm_f16s<<<ggrid, 256, GSMEM>>>(oh, ol, wht + 3 * WSZ, wlt + 3 * WSZ,
                                     out, nullptr, nullptr, nullptr, nullptr,
                                     MROWS, DMODEL, DMODEL, 0);
}